// round 13
// baseline (speedup 1.0000x reference)
#include <cuda_runtime.h>
#include <cuda_fp16.h>
#include <math.h>
#include <stdint.h>

#define Bb 8
#define Cc 512
#define NN 1024
#define HEADS 8
#define DD 64
#define GROUPS 32
#define CPG (Cc / GROUPS)   // 16
#define CN ((size_t)Cc * NN)

typedef __half h16;
typedef __half2 h162;

// -------------------- scratch (device globals) --------------------
static __device__ h16 g_hnb[(size_t)Bb * Cc * NN];
static __device__ h16 g_qb [(size_t)Bb * Cc * NN];
static __device__ h16 g_kb [(size_t)Bb * Cc * NN];
static __device__ h16 g_vb [(size_t)Bb * Cc * NN];
static __device__ h16 g_ohb[(size_t)Bb * NN * Cc];             // [b][q][c]
static __device__ h16 g_wb [(size_t)4 * Cc * Cc];

// -------------------- PTX helpers --------------------
static __device__ __forceinline__ uint32_t smem_u32(const void* p) {
    return (uint32_t)__cvta_generic_to_shared(p);
}
static __device__ __forceinline__ void ldsm4(uint32_t& r0, uint32_t& r1, uint32_t& r2, uint32_t& r3, uint32_t a) {
    asm volatile("ldmatrix.sync.aligned.m8n8.x4.shared.b16 {%0,%1,%2,%3}, [%4];"
                 : "=r"(r0), "=r"(r1), "=r"(r2), "=r"(r3) : "r"(a));
}
static __device__ __forceinline__ void ldsm4t(uint32_t& r0, uint32_t& r1, uint32_t& r2, uint32_t& r3, uint32_t a) {
    asm volatile("ldmatrix.sync.aligned.m8n8.x4.trans.shared.b16 {%0,%1,%2,%3}, [%4];"
                 : "=r"(r0), "=r"(r1), "=r"(r2), "=r"(r3) : "r"(a));
}
static __device__ __forceinline__ void mma16816f(float* c, const uint32_t* a, uint32_t b0, uint32_t b1) {
    asm volatile("mma.sync.aligned.m16n8k16.row.col.f32.f16.f16.f32 "
                 "{%0,%1,%2,%3}, {%4,%5,%6,%7}, {%8,%9}, {%0,%1,%2,%3};"
                 : "+f"(c[0]), "+f"(c[1]), "+f"(c[2]), "+f"(c[3])
                 : "r"(a[0]), "r"(a[1]), "r"(a[2]), "r"(a[3]), "r"(b0), "r"(b1));
}
static __device__ __forceinline__ void mma16816h(uint32_t* c, const uint32_t* a, uint32_t b0, uint32_t b1) {
    asm volatile("mma.sync.aligned.m16n8k16.row.col.f16.f16.f16.f16 "
                 "{%0,%1}, {%2,%3,%4,%5}, {%6,%7}, {%0,%1};"
                 : "+r"(c[0]), "+r"(c[1])
                 : "r"(a[0]), "r"(a[1]), "r"(a[2]), "r"(a[3]), "r"(b0), "r"(b1));
}
static __device__ __forceinline__ uint32_t ex2h2(uint32_t x) {
    uint32_t y; asm volatile("ex2.approx.f16x2 %0, %1;" : "=r"(y) : "r"(x)); return y;
}
static __device__ __forceinline__ uint32_t packh(float a, float b) {
    h162 t = __floats2half2_rn(a, b);
    return *reinterpret_cast<uint32_t*>(&t);
}
static __device__ __forceinline__ uint32_t hadd2u(uint32_t a, uint32_t b) {
    h162 r = __hadd2(*reinterpret_cast<h162*>(&a), *reinterpret_cast<h162*>(&b));
    return *reinterpret_cast<uint32_t*>(&r);
}
#define CP_ASYNC16(saddr, gaddr) \
    asm volatile("cp.async.cg.shared.global [%0], [%1], 16;" :: "r"(saddr), "l"(gaddr))
#define CP_COMMIT() asm volatile("cp.async.commit_group;")
#define CP_WAIT(n)  asm volatile("cp.async.wait_group %0;" :: "n"(n))

// -------------------- merged GroupNorm + weight convert --------------------
__global__ void k_gncvt(const float* __restrict__ x,
                        const float* __restrict__ sc,
                        const float* __restrict__ bi,
                        h16* __restrict__ hn,
                        const float* __restrict__ wq, const float* __restrict__ wk,
                        const float* __restrict__ wv, const float* __restrict__ wo,
                        h16* __restrict__ wout)
{
    __shared__ float red[16];
    if (blockIdx.x >= Bb * GROUPS) {
        const int bid = blockIdx.x - Bb * GROUPS;
        const int m = bid >> 8;
        const int idx = (bid & 255) * 256 + threadIdx.x;
        const float* src = (m == 0) ? wq : (m == 1) ? wk : (m == 2) ? wv : wo;
        float4 f = ((const float4*)src)[idx];
        uint2 u;
        u.x = packh(f.x, f.y);
        u.y = packh(f.z, f.w);
        ((uint2*)(wout + (size_t)m * Cc * Cc))[idx] = u;
        return;
    }

    const int bg = blockIdx.x;
    const int b = bg / GROUPS, g = bg % GROUPS;
    const size_t base = (size_t)b * CN + (size_t)g * CPG * NN;
    const float4* x4 = (const float4*)(x + base);
    h162* h2 = (h162*)(hn + base);
    const int tx = threadIdx.x;

    float s = 0.f, s2 = 0.f;
    for (int i = tx; i < 4096; i += 256) {
        float4 v = x4[i];
        s  += v.x + v.y + v.z + v.w;
        s2 += v.x*v.x + v.y*v.y + v.z*v.z + v.w*v.w;
    }
    #pragma unroll
    for (int o = 16; o; o >>= 1) {
        s  += __shfl_xor_sync(0xffffffffu, s,  o);
        s2 += __shfl_xor_sync(0xffffffffu, s2, o);
    }
    if ((tx & 31) == 0) { red[tx >> 5] = s; red[8 + (tx >> 5)] = s2; }
    __syncthreads();
    float S = 0.f, S2 = 0.f;
    #pragma unroll
    for (int i = 0; i < 8; i++) { S += red[i]; S2 += red[8 + i]; }

    const float inv_n = 1.0f / (CPG * NN);
    const float mu  = S * inv_n;
    const float var = S2 * inv_n - mu * mu;
    const float rstd = rsqrtf(var + 1e-5f);

    for (int i = tx; i < 4096; i += 256) {
        const int cg = i >> 8;
        const float a = sc[g * CPG + cg] * rstd;
        const float c0 = bi[g * CPG + cg] - mu * a;
        float4 v = x4[i];
        h2[i*2 + 0] = __floats2half2_rn(v.x * a + c0, v.y * a + c0);
        h2[i*2 + 1] = __floats2half2_rn(v.z * a + c0, v.w * a + c0);
    }
}

// -------------------- QKV proj mainloop: BK=64, 3-stage ring, wait(1) --------------------
#define QA_ST (128 * 72)     // A stage: [128 m][64+8 k]
#define QB_ST (64 * 136)     // B stage: [64 k][128+8 n]
#define QKV_SMEM ((3 * QA_ST + 3 * QB_ST) * (int)sizeof(h16))   // 107520 B

static __device__ __forceinline__ void proj_mainloop(
    const h16* __restrict__ W, const h16* __restrict__ X,
    int m0, int n0, float acc[4][4][4], h16* sm)
{
    h16* As = sm;                 // 3 stages [128][72]
    h16* Bs = sm + 3 * QA_ST;     // 3 stages [64][136]

    const int tid  = threadIdx.x;
    const int lane = tid & 31;
    const int warp = tid >> 5;
    const int wm = warp >> 2;
    const int wn = warp & 3;

    auto load_stage = [&](int s, int buf) {
        const h16* Wg = W + (size_t)m0 * Cc + s * 64;
        h16* Ab = As + buf * QA_ST;
        #pragma unroll
        for (int j = 0; j < 4; j++) {
            int idx = tid + j * 256;
            int row = idx >> 3, c8 = (idx & 7) * 8;
            CP_ASYNC16(smem_u32(Ab + row * 72 + c8), Wg + (size_t)row * Cc + c8);
        }
        const h16* Xg = X + (size_t)(s * 64) * NN + n0;
        h16* Bbp = Bs + buf * QB_ST;
        #pragma unroll
        for (int j = 0; j < 4; j++) {
            int idx = tid + j * 256;
            int row = idx >> 4, c8 = (idx & 15) * 8;
            CP_ASYNC16(smem_u32(Bbp + row * 136 + c8), Xg + (size_t)row * NN + c8);
        }
    };

    load_stage(0, 0); CP_COMMIT();
    load_stage(1, 1); CP_COMMIT();

    const int arow = lane & 15;
    const int acolh = (lane >> 4) * 8;
    const int brow = ((lane >> 3) & 1) * 8 + (lane & 7);
    const int bcolh = (lane >> 4) * 8;

    #pragma unroll 1
    for (int s = 0; s < 8; s++) {
        if (s < 7) { CP_WAIT(1); } else { CP_WAIT(0); }
        __syncthreads();
        if (s + 2 < 8) {
            int bl = (s + 2) - ((s + 2) / 3) * 3;
            load_stage(s + 2, bl); CP_COMMIT();
        }
        const int bc = s - (s / 3) * 3;
        const h16* Ab = As + bc * QA_ST;
        const h16* Bbp = Bs + bc * QB_ST;
        #pragma unroll
        for (int k16 = 0; k16 < 4; k16++) {
            uint32_t a[4][4], bb[2][4];
            #pragma unroll
            for (int mt = 0; mt < 4; mt++)
                ldsm4(a[mt][0], a[mt][1], a[mt][2], a[mt][3],
                      smem_u32(Ab + (wm * 64 + mt * 16 + arow) * 72 + k16 * 16 + acolh));
            #pragma unroll
            for (int bt = 0; bt < 2; bt++)
                ldsm4t(bb[bt][0], bb[bt][1], bb[bt][2], bb[bt][3],
                       smem_u32(Bbp + (k16 * 16 + brow) * 136 + wn * 32 + bt * 16 + bcolh));
            #pragma unroll
            for (int mi = 0; mi < 4; mi++)
                #pragma unroll
                for (int ni = 0; ni < 4; ni++)
                    mma16816f(acc[mi][ni], a[mi], bb[ni >> 1][(ni & 1) * 2], bb[ni >> 1][(ni & 1) * 2 + 1]);
        }
    }
}

// -------------------- QKV projections (Q pre-scaled by 0.125*log2 e) --------------------
__global__ void __launch_bounds__(256, 2) k_qkv(
    const h16* __restrict__ wb, const h16* __restrict__ hn,
    const float* __restrict__ bq, const float* __restrict__ bk, const float* __restrict__ bv,
    h16* __restrict__ q, h16* __restrict__ k, h16* __restrict__ v)
{
    extern __shared__ h16 smp[];
    const int z = blockIdx.z;
    const int b = z / 3, w = z % 3;
    const h16* W = wb + (size_t)w * Cc * Cc;
    const float* bias = (w == 0) ? bq : (w == 1) ? bk : bv;
    h16* Y = ((w == 0) ? q : (w == 1) ? k : v) + (size_t)b * CN;
    const h16* X = hn + (size_t)b * CN;
    const float oscale = (w == 0) ? 0.18033688011112042f : 1.0f;
    const int m0 = blockIdx.y * 128, n0 = blockIdx.x * 128;

    float acc[4][4][4] = {};
    proj_mainloop(W, X, m0, n0, acc, smp);

    const int lane = threadIdx.x & 31;
    const int warp = threadIdx.x >> 5;
    const int wm = warp >> 2, wn = warp & 3;
    #pragma unroll
    for (int mi = 0; mi < 4; mi++) {
        const int row = m0 + wm * 64 + mi * 16 + (lane >> 2);
        const float b0v = bias[row], b1v = bias[row + 8];
        #pragma unroll
        for (int ni = 0; ni < 4; ni++) {
            const int col = n0 + wn * 32 + ni * 8 + ((lane & 3) << 1);
            *(h162*)(Y + (size_t)row * NN + col) =
                __floats2half2_rn((acc[mi][ni][0] + b0v) * oscale,
                                  (acc[mi][ni][1] + b0v) * oscale);
            *(h162*)(Y + (size_t)(row + 8) * NN + col) =
                __floats2half2_rn((acc[mi][ni][2] + b1v) * oscale,
                                  (acc[mi][ni][3] + b1v) * oscale);
        }
    }
}

// -------------------- fused flash attention (R12, known-good) --------------------
#define QPAD 136
#define QTILE_E (64 * QPAD)
#define KPAD 136
#define KTILE_E (64 * KPAD)
#define ATTN_SMEM ((QTILE_E + 4 * KTILE_E) * (int)sizeof(h16))   // 87040 B

__global__ void __launch_bounds__(128, 2) k_attn(
    const h16* __restrict__ Q, const h16* __restrict__ K,
    const h16* __restrict__ V, h16* __restrict__ OQ)
{
    extern __shared__ h16 sm[];
    h16* Qs = sm;
    h16* Ks = sm + QTILE_E;
    h16* Vs = sm + QTILE_E + 2 * KTILE_E;

    const int bh = blockIdx.y;
    const int b = bh >> 3, h = bh & 7;
    const size_t hb = ((size_t)b * Cc + h * DD) * NN;
    const h16* Qg = Q + hb;
    const h16* Kg = K + hb;
    const h16* Vg = V + hb;
    const int q0 = blockIdx.x * 128;

    const int tid = threadIdx.x;
    const int lane = tid & 31;
    const int warp = tid >> 5;

    #pragma unroll
    for (int j = 0; j < 8; j++) {
        int idx = tid + j * 128;
        int row = idx >> 4, col8 = (idx & 15) * 8;
        CP_ASYNC16(smem_u32(&Qs[row * QPAD + col8]), Qg + (size_t)row * NN + q0 + col8);
    }
    CP_COMMIT();

    auto load_kv = [&](int kt, int buf) {
        const int k0 = kt * 128;
        #pragma unroll
        for (int j = 0; j < 8; j++) {
            int idx = tid + j * 128;
            int row = idx >> 4, col8 = (idx & 15) * 8;
            CP_ASYNC16(smem_u32(&Ks[buf * KTILE_E + row * KPAD + col8]),
                       Kg + (size_t)row * NN + k0 + col8);
            CP_ASYNC16(smem_u32(&Vs[buf * KTILE_E + row * KPAD + col8]),
                       Vg + (size_t)row * NN + k0 + col8);
        }
    };

    load_kv(0, 0);
    CP_COMMIT();

    CP_WAIT(1);
    __syncthreads();

    uint32_t qf[2][4][4];
    {
        const int t_arow = (lane >> 4) * 8 + (lane & 7);
        const int t_acol = ((lane >> 3) & 1) * 8;
        #pragma unroll
        for (int mt = 0; mt < 2; mt++)
            #pragma unroll
            for (int d16 = 0; d16 < 4; d16++)
                ldsm4t(qf[mt][d16][0], qf[mt][d16][1], qf[mt][d16][2], qf[mt][d16][3],
                       smem_u32(&Qs[(d16 * 16 + t_arow) * QPAD + warp * 32 + mt * 16 + t_acol]));
    }

    float lf[2][2] = {};
    float oacc[2][8][4] = {};

    const int t_brow = ((lane >> 3) & 1) * 8 + (lane & 7);
    const int t_bcol = (lane >> 4) * 8;
    const int vrow = ((lane >> 4) & 1) * 8 + (lane & 7);
    const int vcol = ((lane >> 3) & 1) * 8;

    #pragma unroll 1
    for (int kt = 0; kt < 8; kt++) {
        CP_WAIT(0);
        __syncthreads();
        if (kt + 1 < 8) { load_kv(kt + 1, (kt + 1) & 1); CP_COMMIT(); }

        const h16* Kb = Ks + (kt & 1) * KTILE_E;
        const h16* Vb = Vs + (kt & 1) * KTILE_E;

        uint32_t sacc[2][16][2] = {};
        #pragma unroll
        for (int d16 = 0; d16 < 4; d16++) {
            #pragma unroll
            for (int nt = 0; nt < 8; nt++) {
                uint32_t bb[4];
                ldsm4t(bb[0], bb[1], bb[2], bb[3],
                       smem_u32(&Kb[(d16 * 16 + t_brow) * KPAD + nt * 16 + t_bcol]));
                #pragma unroll
                for (int mt = 0; mt < 2; mt++) {
                    mma16816h(sacc[mt][2 * nt],     qf[mt][d16], bb[0], bb[1]);
                    mma16816h(sacc[mt][2 * nt + 1], qf[mt][d16], bb[2], bb[3]);
                }
            }
        }

        #pragma unroll
        for (int t = 0; t < 8; t++) {
            uint32_t pf[2][4];
            #pragma unroll
            for (int mt = 0; mt < 2; mt++) {
                pf[mt][0] = ex2h2(sacc[mt][2 * t][0]);
                pf[mt][1] = ex2h2(sacc[mt][2 * t][1]);
                pf[mt][2] = ex2h2(sacc[mt][2 * t + 1][0]);
                pf[mt][3] = ex2h2(sacc[mt][2 * t + 1][1]);
                uint32_t s0 = hadd2u(pf[mt][0], pf[mt][2]);
                uint32_t s1 = hadd2u(pf[mt][1], pf[mt][3]);
                float2 f0 = __half22float2(*reinterpret_cast<h162*>(&s0));
                float2 f1 = __half22float2(*reinterpret_cast<h162*>(&s1));
                lf[mt][0] += f0.x + f0.y;
                lf[mt][1] += f1.x + f1.y;
            }
            #pragma unroll
            for (int nt = 0; nt < 4; nt++) {
                uint32_t bb[4];
                ldsm4(bb[0], bb[1], bb[2], bb[3],
                      smem_u32(&Vb[(nt * 16 + vrow) * KPAD + t * 16 + vcol]));
                #pragma unroll
                for (int mt = 0; mt < 2; mt++) {
                    mma16816f(oacc[mt][2 * nt],     pf[mt], bb[0], bb[1]);
                    mma16816f(oacc[mt][2 * nt + 1], pf[mt], bb[2], bb[3]);
                }
            }
        }
    }

    #pragma unroll
    for (int mt = 0; mt < 2; mt++) {
        float l0 = lf[mt][0], l1 = lf[mt][1];
        l0 += __shfl_xor_sync(0xffffffffu, l0, 1);
        l0 += __shfl_xor_sync(0xffffffffu, l0, 2);
        l1 += __shfl_xor_sync(0xffffffffu, l1, 1);
        l1 += __shfl_xor_sync(0xffffffffu, l1, 2);
        const float inv0 = 1.0f / l0;
        const float inv1 = 1.0f / l1;
        const int qrow = q0 + warp * 32 + mt * 16 + (lane >> 2);
        h16* p0 = OQ + ((size_t)b * NN + qrow) * Cc + h * DD + ((lane & 3) << 1);
        h16* p1 = p0 + (size_t)8 * Cc;
        #pragma unroll
        for (int j = 0; j < 8; j++) {
            *(h162*)(p0 + j * 8) = __floats2half2_rn(oacc[mt][j][0] * inv0, oacc[mt][j][1] * inv0);
            *(h162*)(p1 + j * 8) = __floats2half2_rn(oacc[mt][j][2] * inv1, oacc[mt][j][3] * inv1);
        }
    }
}

// -------------------- out-projection: BK=64, 3-stage ring, wait(1) --------------------
#define OB_ST (128 * 72)
#define OPROJ_SMEM ((3 * QA_ST + 3 * OB_ST) * (int)sizeof(h16))   // 110592 B

__global__ void __launch_bounds__(256, 2) k_oproj(
    const h16* __restrict__ wb, const h16* __restrict__ ohq,
    const float* __restrict__ bo, const float* __restrict__ xres,
    float* __restrict__ out)
{
    extern __shared__ h16 smo[];
    h16* As = smo;                 // 3 stages [128][72]
    h16* Bs = smo + 3 * QA_ST;     // 3 stages [128][72]

    const int b = blockIdx.z;
    const h16* W = wb + (size_t)3 * Cc * Cc;
    const h16* Xq = ohq + (size_t)b * NN * Cc;
    const float* R = xres + (size_t)b * CN;
    float* Y = out + (size_t)b * CN;
    const int m0 = blockIdx.y * 128, n0 = blockIdx.x * 128;

    const int tid = threadIdx.x;
    const int lane = tid & 31;
    const int warp = tid >> 5;
    const int wm = warp >> 2, wn = warp & 3;

    auto load_stage = [&](int s, int buf) {
        h16* Ab = As + buf * QA_ST;
        h16* Bbp = Bs + buf * OB_ST;
        #pragma unroll
        for (int j = 0; j < 4; j++) {
            int idx = tid + j * 256;
            int row = idx >> 3, c8 = (idx & 7) * 8;
            CP_ASYNC16(smem_u32(Ab + row * 72 + c8),
                       W + (size_t)(m0 + row) * Cc + s * 64 + c8);
            CP_ASYNC16(smem_u32(Bbp + row * 72 + c8),
                       Xq + (size_t)(n0 + row) * Cc + s * 64 + c8);
        }
    };

    load_stage(0, 0); CP_COMMIT();
    load_stage(1, 1); CP_COMMIT();

    const int arow = lane & 15;
    const int acolh = (lane >> 4) * 8;
    const int brow = ((lane >> 4) & 1) * 8 + (lane & 7);
    const int bcol = ((lane >> 3) & 1) * 8;

    float acc[4][4][4] = {};

    #pragma unroll 1
    for (int s = 0; s < 8; s++) {
        if (s < 7) { CP_WAIT(1); } else { CP_WAIT(0); }
        __syncthreads();
        if (s + 2 < 8) {
            int bl = (s + 2) - ((s + 2) / 3) * 3;
            load_stage(s + 2, bl); CP_COMMIT();
        }
        const int bc = s - (s / 3) * 3;
        const h16* Ab = As + bc * QA_ST;
        const h16* Bbp = Bs + bc * OB_ST;
        #pragma unroll
        for (int k16 = 0; k16 < 4; k16++) {
            uint32_t a[4][4], bb[2][4];
            #pragma unroll
            for (int mt = 0; mt < 4; mt++)
                ldsm4(a[mt][0], a[mt][1], a[mt][2], a[mt][3],
                      smem_u32(Ab + (wm * 64 + mt * 16 + arow) * 72 + k16 * 16 + acolh));
            #pragma unroll
            for (int nt = 0; nt < 2; nt++)
                ldsm4(bb[nt][0], bb[nt][1], bb[nt][2], bb[nt][3],
                      smem_u32(Bbp + (wn * 32 + nt * 16 + brow) * 72 + k16 * 16 + bcol));
            #pragma unroll
            for (int mi = 0; mi < 4; mi++)
                #pragma unroll
                for (int ni = 0; ni < 4; ni++)
                    mma16816f(acc[mi][ni], a[mi], bb[ni >> 1][(ni & 1) * 2], bb[ni >> 1][(ni & 1) * 2 + 1]);
        }
    }

    #pragma unroll
    for (int mi = 0; mi < 4; mi++) {
        const int row = m0 + wm * 64 + mi * 16 + (lane >> 2);
        const float b0v = bo[row], b1v = bo[row + 8];
        #pragma unroll
        for (int ni = 0; ni < 4; ni++) {
            const int col = n0 + wn * 32 + ni * 8 + ((lane & 3) << 1);
            float2 r0 = *(const float2*)(R + (size_t)row * NN + col);
            float2 r1 = *(const float2*)(R + (size_t)(row + 8) * NN + col);
            float2 o0, o1;
            o0.x = acc[mi][ni][0] + b0v + r0.x;
            o0.y = acc[mi][ni][1] + b0v + r0.y;
            o1.x = acc[mi][ni][2] + b1v + r1.x;
            o1.y = acc[mi][ni][3] + b1v + r1.y;
            *(float2*)(Y + (size_t)row * NN + col) = o0;
            *(float2*)(Y + (size_t)(row + 8) * NN + col) = o1;
        }
    }
}

// -------------------- launch --------------------
extern "C" void kernel_launch(void* const* d_in, const int* in_sizes, int n_in,
                              void* d_out, int out_size)
{
    const float* x        = (const float*)d_in[0];
    const float* gn_scale = (const float*)d_in[1];
    const float* gn_bias  = (const float*)d_in[2];
    const float* wq = (const float*)d_in[3];
    const float* bq = (const float*)d_in[4];
    const float* wk = (const float*)d_in[5];
    const float* bk = (const float*)d_in[6];
    const float* wv = (const float*)d_in[7];
    const float* bv = (const float*)d_in[8];
    const float* wo = (const float*)d_in[9];
    const float* bo = (const float*)d_in[10];
    float* out = (float*)d_out;

    h16 *hn, *q, *k, *v, *oh, *wb;
    cudaGetSymbolAddress((void**)&hn, g_hnb);
    cudaGetSymbolAddress((void**)&q,  g_qb);
    cudaGetSymbolAddress((void**)&k,  g_kb);
    cudaGetSymbolAddress((void**)&v,  g_vb);
    cudaGetSymbolAddress((void**)&oh, g_ohb);
    cudaGetSymbolAddress((void**)&wb, g_wb);

    static int attrs_set = 0;
    if (!attrs_set) {
        cudaFuncSetAttribute(k_attn,  cudaFuncAttributeMaxDynamicSharedMemorySize, ATTN_SMEM);
        cudaFuncSetAttribute(k_qkv,   cudaFuncAttributeMaxDynamicSharedMemorySize, QKV_SMEM);
        cudaFuncSetAttribute(k_oproj, cudaFuncAttributeMaxDynamicSharedMemorySize, OPROJ_SMEM);
        attrs_set = 1;
    }

    // 1. GroupNorm -> fp16 (+ weight convert, merged)
    k_gncvt<<<Bb * GROUPS + 1024, 256>>>(x, gn_scale, gn_bias, hn, wq, wk, wv, wo, wb);

    // 2. Q/K/V projections (Q pre-scaled by 0.125*log2 e)
    k_qkv<<<dim3(NN / 128, Cc / 128, Bb * 3), 256, QKV_SMEM>>>(wb, hn, bq, bk, bv, q, k, v);

    // 3. fused attention (4 warps x 32 q-rows, 128-wide KV)
    k_attn<<<dim3(NN / 128, Bb * HEADS), 128, ATTN_SMEM>>>(q, k, v, oh);

    // 4. out = wo * oh + bo + x
    k_oproj<<<dim3(NN / 128, Cc / 128, Bb), 256, OPROJ_SMEM>>>(wb, oh, bo, x, out);
}

// round 14
// speedup vs baseline: 1.0306x; 1.0306x over previous
#include <cuda_runtime.h>
#include <cuda_fp16.h>
#include <math.h>
#include <stdint.h>

#define Bb 8
#define Cc 512
#define NN 1024
#define HEADS 8
#define DD 64
#define GROUPS 32
#define CPG (Cc / GROUPS)   // 16
#define CN ((size_t)Cc * NN)

typedef __half h16;
typedef __half2 h162;

// -------------------- scratch (device globals) --------------------
static __device__ h16 g_hnb[(size_t)Bb * Cc * NN];
static __device__ h16 g_qb [(size_t)Bb * Cc * NN];
static __device__ h16 g_kb [(size_t)Bb * Cc * NN];
static __device__ h16 g_vb [(size_t)Bb * Cc * NN];
static __device__ h16 g_ohb[(size_t)Bb * NN * Cc];             // [b][q][c]
static __device__ h16 g_wb [(size_t)4 * Cc * Cc];

// -------------------- PTX helpers --------------------
static __device__ __forceinline__ uint32_t smem_u32(const void* p) {
    return (uint32_t)__cvta_generic_to_shared(p);
}
static __device__ __forceinline__ void ldsm4(uint32_t& r0, uint32_t& r1, uint32_t& r2, uint32_t& r3, uint32_t a) {
    asm volatile("ldmatrix.sync.aligned.m8n8.x4.shared.b16 {%0,%1,%2,%3}, [%4];"
                 : "=r"(r0), "=r"(r1), "=r"(r2), "=r"(r3) : "r"(a));
}
static __device__ __forceinline__ void ldsm4t(uint32_t& r0, uint32_t& r1, uint32_t& r2, uint32_t& r3, uint32_t a) {
    asm volatile("ldmatrix.sync.aligned.m8n8.x4.trans.shared.b16 {%0,%1,%2,%3}, [%4];"
                 : "=r"(r0), "=r"(r1), "=r"(r2), "=r"(r3) : "r"(a));
}
static __device__ __forceinline__ void mma16816f(float* c, const uint32_t* a, uint32_t b0, uint32_t b1) {
    asm volatile("mma.sync.aligned.m16n8k16.row.col.f32.f16.f16.f32 "
                 "{%0,%1,%2,%3}, {%4,%5,%6,%7}, {%8,%9}, {%0,%1,%2,%3};"
                 : "+f"(c[0]), "+f"(c[1]), "+f"(c[2]), "+f"(c[3])
                 : "r"(a[0]), "r"(a[1]), "r"(a[2]), "r"(a[3]), "r"(b0), "r"(b1));
}
static __device__ __forceinline__ void mma16816h(uint32_t* c, const uint32_t* a, uint32_t b0, uint32_t b1) {
    asm volatile("mma.sync.aligned.m16n8k16.row.col.f16.f16.f16.f16 "
                 "{%0,%1}, {%2,%3,%4,%5}, {%6,%7}, {%0,%1};"
                 : "+r"(c[0]), "+r"(c[1])
                 : "r"(a[0]), "r"(a[1]), "r"(a[2]), "r"(a[3]), "r"(b0), "r"(b1));
}
static __device__ __forceinline__ uint32_t ex2h2(uint32_t x) {
    uint32_t y; asm volatile("ex2.approx.f16x2 %0, %1;" : "=r"(y) : "r"(x)); return y;
}
static __device__ __forceinline__ uint32_t packh(float a, float b) {
    h162 t = __floats2half2_rn(a, b);
    return *reinterpret_cast<uint32_t*>(&t);
}
static __device__ __forceinline__ uint32_t hadd2u(uint32_t a, uint32_t b) {
    h162 r = __hadd2(*reinterpret_cast<h162*>(&a), *reinterpret_cast<h162*>(&b));
    return *reinterpret_cast<uint32_t*>(&r);
}
#define CP_ASYNC16(saddr, gaddr) \
    asm volatile("cp.async.cg.shared.global [%0], [%1], 16;" :: "r"(saddr), "l"(gaddr))
#define CP_COMMIT() asm volatile("cp.async.commit_group;")
#define CP_WAIT(n)  asm volatile("cp.async.wait_group %0;" :: "n"(n))

// -------------------- merged GroupNorm + weight convert --------------------
__global__ void k_gncvt(const float* __restrict__ x,
                        const float* __restrict__ sc,
                        const float* __restrict__ bi,
                        h16* __restrict__ hn,
                        const float* __restrict__ wq, const float* __restrict__ wk,
                        const float* __restrict__ wv, const float* __restrict__ wo,
                        h16* __restrict__ wout)
{
    __shared__ float red[16];
    if (blockIdx.x >= Bb * GROUPS) {
        const int bid = blockIdx.x - Bb * GROUPS;
        const int m = bid >> 8;
        const int idx = (bid & 255) * 256 + threadIdx.x;
        const float* src = (m == 0) ? wq : (m == 1) ? wk : (m == 2) ? wv : wo;
        float4 f = ((const float4*)src)[idx];
        uint2 u;
        u.x = packh(f.x, f.y);
        u.y = packh(f.z, f.w);
        ((uint2*)(wout + (size_t)m * Cc * Cc))[idx] = u;
        return;
    }

    const int bg = blockIdx.x;
    const int b = bg / GROUPS, g = bg % GROUPS;
    const size_t base = (size_t)b * CN + (size_t)g * CPG * NN;
    const float4* x4 = (const float4*)(x + base);
    h162* h2 = (h162*)(hn + base);
    const int tx = threadIdx.x;

    float s = 0.f, s2 = 0.f;
    for (int i = tx; i < 4096; i += 256) {
        float4 v = x4[i];
        s  += v.x + v.y + v.z + v.w;
        s2 += v.x*v.x + v.y*v.y + v.z*v.z + v.w*v.w;
    }
    #pragma unroll
    for (int o = 16; o; o >>= 1) {
        s  += __shfl_xor_sync(0xffffffffu, s,  o);
        s2 += __shfl_xor_sync(0xffffffffu, s2, o);
    }
    if ((tx & 31) == 0) { red[tx >> 5] = s; red[8 + (tx >> 5)] = s2; }
    __syncthreads();
    float S = 0.f, S2 = 0.f;
    #pragma unroll
    for (int i = 0; i < 8; i++) { S += red[i]; S2 += red[8 + i]; }

    const float inv_n = 1.0f / (CPG * NN);
    const float mu  = S * inv_n;
    const float var = S2 * inv_n - mu * mu;
    const float rstd = rsqrtf(var + 1e-5f);

    for (int i = tx; i < 4096; i += 256) {
        const int cg = i >> 8;
        const float a = sc[g * CPG + cg] * rstd;
        const float c0 = bi[g * CPG + cg] - mu * a;
        float4 v = x4[i];
        h2[i*2 + 0] = __floats2half2_rn(v.x * a + c0, v.y * a + c0);
        h2[i*2 + 1] = __floats2half2_rn(v.z * a + c0, v.w * a + c0);
    }
}

// -------------------- QKV projections: 128 threads, 64x128 tile, 4 CTAs/SM --------------------
#define QA_ST (64 * 72)      // A stage: [64 m][64+8 k]
#define QB_ST (64 * 136)     // B stage: [64 k][128+8 n]
#define QKV_SMEM ((2 * QA_ST + 2 * QB_ST) * (int)sizeof(h16))   // 53248 B

__global__ void __launch_bounds__(128, 4) k_qkv(
    const h16* __restrict__ wb, const h16* __restrict__ hn,
    const float* __restrict__ bq, const float* __restrict__ bk, const float* __restrict__ bv,
    h16* __restrict__ q, h16* __restrict__ k, h16* __restrict__ v)
{
    extern __shared__ h16 smp[];
    h16* As = smp;                // 2 stages [64][72]
    h16* Bs = smp + 2 * QA_ST;    // 2 stages [64][136]

    const int z = blockIdx.z;
    const int b = z / 3, w = z % 3;
    const h16* W = wb + (size_t)w * Cc * Cc;
    const float* bias = (w == 0) ? bq : (w == 1) ? bk : bv;
    h16* Y = ((w == 0) ? q : (w == 1) ? k : v) + (size_t)b * CN;
    const h16* X = hn + (size_t)b * CN;
    const float oscale = (w == 0) ? 0.18033688011112042f : 1.0f;
    const int m0 = blockIdx.y * 64, n0 = blockIdx.x * 128;

    const int tid = threadIdx.x;
    const int lane = tid & 31;
    const int wn = tid >> 5;          // 0..3, warp's 32-n slice

    auto load_stage = [&](int s, int buf) {
        const h16* Wg = W + (size_t)m0 * Cc + s * 64;
        h16* Ab = As + buf * QA_ST;
        #pragma unroll
        for (int j = 0; j < 4; j++) {
            int idx = tid + j * 128;
            int row = idx >> 3, c8 = (idx & 7) * 8;
            CP_ASYNC16(smem_u32(Ab + row * 72 + c8), Wg + (size_t)row * Cc + c8);
        }
        const h16* Xg = X + (size_t)(s * 64) * NN + n0;
        h16* Bbp = Bs + buf * QB_ST;
        #pragma unroll
        for (int j = 0; j < 8; j++) {
            int idx = tid + j * 128;
            int row = idx >> 4, c8 = (idx & 15) * 8;
            CP_ASYNC16(smem_u32(Bbp + row * 136 + c8), Xg + (size_t)row * NN + c8);
        }
    };

    load_stage(0, 0);
    CP_COMMIT();

    const int arow = lane & 15;
    const int acolh = (lane >> 4) * 8;
    const int brow = ((lane >> 3) & 1) * 8 + (lane & 7);
    const int bcolh = (lane >> 4) * 8;

    float acc[4][4][4] = {};

    #pragma unroll 1
    for (int s = 0; s < 8; s++) {
        CP_WAIT(0);
        __syncthreads();
        if (s + 1 < 8) { load_stage(s + 1, (s + 1) & 1); CP_COMMIT(); }
        const h16* Ab = As + (s & 1) * QA_ST;
        const h16* Bbp = Bs + (s & 1) * QB_ST;
        #pragma unroll
        for (int k16 = 0; k16 < 4; k16++) {
            uint32_t a[4][4], bb[2][4];
            #pragma unroll
            for (int mt = 0; mt < 4; mt++)
                ldsm4(a[mt][0], a[mt][1], a[mt][2], a[mt][3],
                      smem_u32(Ab + (mt * 16 + arow) * 72 + k16 * 16 + acolh));
            #pragma unroll
            for (int bt = 0; bt < 2; bt++)
                ldsm4t(bb[bt][0], bb[bt][1], bb[bt][2], bb[bt][3],
                       smem_u32(Bbp + (k16 * 16 + brow) * 136 + wn * 32 + bt * 16 + bcolh));
            #pragma unroll
            for (int mt = 0; mt < 4; mt++)
                #pragma unroll
                for (int ni = 0; ni < 4; ni++)
                    mma16816f(acc[mt][ni], a[mt], bb[ni >> 1][(ni & 1) * 2], bb[ni >> 1][(ni & 1) * 2 + 1]);
        }
    }

    #pragma unroll
    for (int mt = 0; mt < 4; mt++) {
        const int row = m0 + mt * 16 + (lane >> 2);
        const float b0v = bias[row], b1v = bias[row + 8];
        #pragma unroll
        for (int ni = 0; ni < 4; ni++) {
            const int col = n0 + wn * 32 + ni * 8 + ((lane & 3) << 1);
            *(h162*)(Y + (size_t)row * NN + col) =
                __floats2half2_rn((acc[mt][ni][0] + b0v) * oscale,
                                  (acc[mt][ni][1] + b0v) * oscale);
            *(h162*)(Y + (size_t)(row + 8) * NN + col) =
                __floats2half2_rn((acc[mt][ni][2] + b1v) * oscale,
                                  (acc[mt][ni][3] + b1v) * oscale);
        }
    }
}

// -------------------- fused flash attention (R12, known-good) --------------------
#define QPAD 136
#define QTILE_E (64 * QPAD)
#define KPAD 136
#define KTILE_E (64 * KPAD)
#define ATTN_SMEM ((QTILE_E + 4 * KTILE_E) * (int)sizeof(h16))   // 87040 B

__global__ void __launch_bounds__(128, 2) k_attn(
    const h16* __restrict__ Q, const h16* __restrict__ K,
    const h16* __restrict__ V, h16* __restrict__ OQ)
{
    extern __shared__ h16 sm[];
    h16* Qs = sm;
    h16* Ks = sm + QTILE_E;
    h16* Vs = sm + QTILE_E + 2 * KTILE_E;

    const int bh = blockIdx.y;
    const int b = bh >> 3, h = bh & 7;
    const size_t hb = ((size_t)b * Cc + h * DD) * NN;
    const h16* Qg = Q + hb;
    const h16* Kg = K + hb;
    const h16* Vg = V + hb;
    const int q0 = blockIdx.x * 128;

    const int tid = threadIdx.x;
    const int lane = tid & 31;
    const int warp = tid >> 5;

    #pragma unroll
    for (int j = 0; j < 8; j++) {
        int idx = tid + j * 128;
        int row = idx >> 4, col8 = (idx & 15) * 8;
        CP_ASYNC16(smem_u32(&Qs[row * QPAD + col8]), Qg + (size_t)row * NN + q0 + col8);
    }
    CP_COMMIT();

    auto load_kv = [&](int kt, int buf) {
        const int k0 = kt * 128;
        #pragma unroll
        for (int j = 0; j < 8; j++) {
            int idx = tid + j * 128;
            int row = idx >> 4, col8 = (idx & 15) * 8;
            CP_ASYNC16(smem_u32(&Ks[buf * KTILE_E + row * KPAD + col8]),
                       Kg + (size_t)row * NN + k0 + col8);
            CP_ASYNC16(smem_u32(&Vs[buf * KTILE_E + row * KPAD + col8]),
                       Vg + (size_t)row * NN + k0 + col8);
        }
    };

    load_kv(0, 0);
    CP_COMMIT();

    CP_WAIT(1);
    __syncthreads();

    uint32_t qf[2][4][4];
    {
        const int t_arow = (lane >> 4) * 8 + (lane & 7);
        const int t_acol = ((lane >> 3) & 1) * 8;
        #pragma unroll
        for (int mt = 0; mt < 2; mt++)
            #pragma unroll
            for (int d16 = 0; d16 < 4; d16++)
                ldsm4t(qf[mt][d16][0], qf[mt][d16][1], qf[mt][d16][2], qf[mt][d16][3],
                       smem_u32(&Qs[(d16 * 16 + t_arow) * QPAD + warp * 32 + mt * 16 + t_acol]));
    }

    float lf[2][2] = {};
    float oacc[2][8][4] = {};

    const int t_brow = ((lane >> 3) & 1) * 8 + (lane & 7);
    const int t_bcol = (lane >> 4) * 8;
    const int vrow = ((lane >> 4) & 1) * 8 + (lane & 7);
    const int vcol = ((lane >> 3) & 1) * 8;

    #pragma unroll 1
    for (int kt = 0; kt < 8; kt++) {
        CP_WAIT(0);
        __syncthreads();
        if (kt + 1 < 8) { load_kv(kt + 1, (kt + 1) & 1); CP_COMMIT(); }

        const h16* Kb = Ks + (kt & 1) * KTILE_E;
        const h16* Vb = Vs + (kt & 1) * KTILE_E;

        uint32_t sacc[2][16][2] = {};
        #pragma unroll
        for (int d16 = 0; d16 < 4; d16++) {
            #pragma unroll
            for (int nt = 0; nt < 8; nt++) {
                uint32_t bb[4];
                ldsm4t(bb[0], bb[1], bb[2], bb[3],
                       smem_u32(&Kb[(d16 * 16 + t_brow) * KPAD + nt * 16 + t_bcol]));
                #pragma unroll
                for (int mt = 0; mt < 2; mt++) {
                    mma16816h(sacc[mt][2 * nt],     qf[mt][d16], bb[0], bb[1]);
                    mma16816h(sacc[mt][2 * nt + 1], qf[mt][d16], bb[2], bb[3]);
                }
            }
        }

        #pragma unroll
        for (int t = 0; t < 8; t++) {
            uint32_t pf[2][4];
            #pragma unroll
            for (int mt = 0; mt < 2; mt++) {
                pf[mt][0] = ex2h2(sacc[mt][2 * t][0]);
                pf[mt][1] = ex2h2(sacc[mt][2 * t][1]);
                pf[mt][2] = ex2h2(sacc[mt][2 * t + 1][0]);
                pf[mt][3] = ex2h2(sacc[mt][2 * t + 1][1]);
                uint32_t s0 = hadd2u(pf[mt][0], pf[mt][2]);
                uint32_t s1 = hadd2u(pf[mt][1], pf[mt][3]);
                float2 f0 = __half22float2(*reinterpret_cast<h162*>(&s0));
                float2 f1 = __half22float2(*reinterpret_cast<h162*>(&s1));
                lf[mt][0] += f0.x + f0.y;
                lf[mt][1] += f1.x + f1.y;
            }
            #pragma unroll
            for (int nt = 0; nt < 4; nt++) {
                uint32_t bb[4];
                ldsm4(bb[0], bb[1], bb[2], bb[3],
                      smem_u32(&Vb[(nt * 16 + vrow) * KPAD + t * 16 + vcol]));
                #pragma unroll
                for (int mt = 0; mt < 2; mt++) {
                    mma16816f(oacc[mt][2 * nt],     pf[mt], bb[0], bb[1]);
                    mma16816f(oacc[mt][2 * nt + 1], pf[mt], bb[2], bb[3]);
                }
            }
        }
    }

    #pragma unroll
    for (int mt = 0; mt < 2; mt++) {
        float l0 = lf[mt][0], l1 = lf[mt][1];
        l0 += __shfl_xor_sync(0xffffffffu, l0, 1);
        l0 += __shfl_xor_sync(0xffffffffu, l0, 2);
        l1 += __shfl_xor_sync(0xffffffffu, l1, 1);
        l1 += __shfl_xor_sync(0xffffffffu, l1, 2);
        const float inv0 = 1.0f / l0;
        const float inv1 = 1.0f / l1;
        const int qrow = q0 + warp * 32 + mt * 16 + (lane >> 2);
        h16* p0 = OQ + ((size_t)b * NN + qrow) * Cc + h * DD + ((lane & 3) << 1);
        h16* p1 = p0 + (size_t)8 * Cc;
        #pragma unroll
        for (int j = 0; j < 8; j++) {
            *(h162*)(p0 + j * 8) = __floats2half2_rn(oacc[mt][j][0] * inv0, oacc[mt][j][1] * inv0);
            *(h162*)(p1 + j * 8) = __floats2half2_rn(oacc[mt][j][2] * inv1, oacc[mt][j][3] * inv1);
        }
    }
}

// -------------------- out-projection: 128 threads, 64x128 tile, 4 CTAs/SM --------------------
#define OB_ST (128 * 72)     // B stage: [128 q][64+8 k]
#define OPROJ_SMEM ((2 * QA_ST + 2 * OB_ST) * (int)sizeof(h16))   // 55296 B

__global__ void __launch_bounds__(128, 4) k_oproj(
    const h16* __restrict__ wb, const h16* __restrict__ ohq,
    const float* __restrict__ bo, const float* __restrict__ xres,
    float* __restrict__ out)
{
    extern __shared__ h16 smo[];
    h16* As = smo;                 // 2 stages [64][72]
    h16* Bs = smo + 2 * QA_ST;     // 2 stages [128][72]

    const int b = blockIdx.z;
    const h16* W = wb + (size_t)3 * Cc * Cc;
    const h16* Xq = ohq + (size_t)b * NN * Cc;
    const float* R = xres + (size_t)b * CN;
    float* Y = out + (size_t)b * CN;
    const int m0 = blockIdx.y * 64, n0 = blockIdx.x * 128;

    const int tid = threadIdx.x;
    const int lane = tid & 31;
    const int wn = tid >> 5;          // 0..3

    auto load_stage = [&](int s, int buf) {
        h16* Ab = As + buf * QA_ST;
        h16* Bbp = Bs + buf * OB_ST;
        #pragma unroll
        for (int j = 0; j < 4; j++) {
            int idx = tid + j * 128;
            int row = idx >> 3, c8 = (idx & 7) * 8;
            CP_ASYNC16(smem_u32(Ab + row * 72 + c8),
                       W + (size_t)(m0 + row) * Cc + s * 64 + c8);
        }
        #pragma unroll
        for (int j = 0; j < 8; j++) {
            int idx = tid + j * 128;
            int row = idx >> 3, c8 = (idx & 7) * 8;
            CP_ASYNC16(smem_u32(Bbp + row * 72 + c8),
                       Xq + (size_t)(n0 + row) * Cc + s * 64 + c8);
        }
    };

    load_stage(0, 0);
    CP_COMMIT();

    const int arow = lane & 15;
    const int acolh = (lane >> 4) * 8;
    const int brow = ((lane >> 4) & 1) * 8 + (lane & 7);
    const int bcol = ((lane >> 3) & 1) * 8;

    float acc[4][4][4] = {};

    #pragma unroll 1
    for (int s = 0; s < 8; s++) {
        CP_WAIT(0);
        __syncthreads();
        if (s + 1 < 8) { load_stage(s + 1, (s + 1) & 1); CP_COMMIT(); }
        const h16* Ab = As + (s & 1) * QA_ST;
        const h16* Bbp = Bs + (s & 1) * OB_ST;
        #pragma unroll
        for (int k16 = 0; k16 < 4; k16++) {
            uint32_t a[4][4], bb[2][4];
            #pragma unroll
            for (int mt = 0; mt < 4; mt++)
                ldsm4(a[mt][0], a[mt][1], a[mt][2], a[mt][3],
                      smem_u32(Ab + (mt * 16 + arow) * 72 + k16 * 16 + acolh));
            #pragma unroll
            for (int nt = 0; nt < 2; nt++)
                ldsm4(bb[nt][0], bb[nt][1], bb[nt][2], bb[nt][3],
                      smem_u32(Bbp + (wn * 32 + nt * 16 + brow) * 72 + k16 * 16 + bcol));
            #pragma unroll
            for (int mt = 0; mt < 4; mt++)
                #pragma unroll
                for (int ni = 0; ni < 4; ni++)
                    mma16816f(acc[mt][ni], a[mt], bb[ni >> 1][(ni & 1) * 2], bb[ni >> 1][(ni & 1) * 2 + 1]);
        }
    }

    #pragma unroll
    for (int mt = 0; mt < 4; mt++) {
        const int row = m0 + mt * 16 + (lane >> 2);
        const float b0v = bo[row], b1v = bo[row + 8];
        #pragma unroll
        for (int ni = 0; ni < 4; ni++) {
            const int col = n0 + wn * 32 + ni * 8 + ((lane & 3) << 1);
            float2 r0 = *(const float2*)(R + (size_t)row * NN + col);
            float2 r1 = *(const float2*)(R + (size_t)(row + 8) * NN + col);
            float2 o0, o1;
            o0.x = acc[mt][ni][0] + b0v + r0.x;
            o0.y = acc[mt][ni][1] + b0v + r0.y;
            o1.x = acc[mt][ni][2] + b1v + r1.x;
            o1.y = acc[mt][ni][3] + b1v + r1.y;
            *(float2*)(Y + (size_t)row * NN + col) = o0;
            *(float2*)(Y + (size_t)(row + 8) * NN + col) = o1;
        }
    }
}

// -------------------- launch --------------------
extern "C" void kernel_launch(void* const* d_in, const int* in_sizes, int n_in,
                              void* d_out, int out_size)
{
    const float* x        = (const float*)d_in[0];
    const float* gn_scale = (const float*)d_in[1];
    const float* gn_bias  = (const float*)d_in[2];
    const float* wq = (const float*)d_in[3];
    const float* bq = (const float*)d_in[4];
    const float* wk = (const float*)d_in[5];
    const float* bk = (const float*)d_in[6];
    const float* wv = (const float*)d_in[7];
    const float* bv = (const float*)d_in[8];
    const float* wo = (const float*)d_in[9];
    const float* bo = (const float*)d_in[10];
    float* out = (float*)d_out;

    h16 *hn, *q, *k, *v, *oh, *wb;
    cudaGetSymbolAddress((void**)&hn, g_hnb);
    cudaGetSymbolAddress((void**)&q,  g_qb);
    cudaGetSymbolAddress((void**)&k,  g_kb);
    cudaGetSymbolAddress((void**)&v,  g_vb);
    cudaGetSymbolAddress((void**)&oh, g_ohb);
    cudaGetSymbolAddress((void**)&wb, g_wb);

    static int attrs_set = 0;
    if (!attrs_set) {
        cudaFuncSetAttribute(k_attn,  cudaFuncAttributeMaxDynamicSharedMemorySize, ATTN_SMEM);
        cudaFuncSetAttribute(k_qkv,   cudaFuncAttributeMaxDynamicSharedMemorySize, QKV_SMEM);
        cudaFuncSetAttribute(k_oproj, cudaFuncAttributeMaxDynamicSharedMemorySize, OPROJ_SMEM);
        attrs_set = 1;
    }

    // 1. GroupNorm -> fp16 (+ weight convert, merged)
    k_gncvt<<<Bb * GROUPS + 1024, 256>>>(x, gn_scale, gn_bias, hn, wq, wk, wv, wo, wb);

    // 2. Q/K/V projections (Q pre-scaled by 0.125*log2 e); 64x128 tiles, 4 CTAs/SM
    k_qkv<<<dim3(NN / 128, Cc / 64, Bb * 3), 128, QKV_SMEM>>>(wb, hn, bq, bk, bv, q, k, v);

    // 3. fused attention (4 warps x 32 q-rows, 128-wide KV)
    k_attn<<<dim3(NN / 128, Bb * HEADS), 128, ATTN_SMEM>>>(q, k, v, oh);

    // 4. out = wo * oh + bo + x; 64x128 tiles, 4 CTAs/SM
    k_oproj<<<dim3(NN / 128, Cc / 64, Bb), 128, OPROJ_SMEM>>>(wb, oh, bo, x, out);
}

// round 16
// speedup vs baseline: 1.0531x; 1.0219x over previous
#include <cuda_runtime.h>
#include <cuda_fp16.h>
#include <math.h>
#include <stdint.h>

#define Bb 8
#define Cc 512
#define NN 1024
#define HEADS 8
#define DD 64
#define GROUPS 32
#define CPG (Cc / GROUPS)   // 16
#define CN ((size_t)Cc * NN)

typedef __half h16;
typedef __half2 h162;

// -------------------- scratch (device globals) --------------------
static __device__ h16 g_hnb[(size_t)Bb * Cc * NN];
static __device__ h16 g_qb [(size_t)Bb * Cc * NN];
static __device__ h16 g_kb [(size_t)Bb * Cc * NN];
static __device__ h16 g_vb [(size_t)Bb * Cc * NN];
static __device__ h16 g_ohb[(size_t)Bb * NN * Cc];             // [b][q][c]
static __device__ h16 g_wb [(size_t)4 * Cc * Cc];

// -------------------- PTX helpers --------------------
static __device__ __forceinline__ uint32_t smem_u32(const void* p) {
    return (uint32_t)__cvta_generic_to_shared(p);
}
static __device__ __forceinline__ void ldsm4(uint32_t& r0, uint32_t& r1, uint32_t& r2, uint32_t& r3, uint32_t a) {
    asm volatile("ldmatrix.sync.aligned.m8n8.x4.shared.b16 {%0,%1,%2,%3}, [%4];"
                 : "=r"(r0), "=r"(r1), "=r"(r2), "=r"(r3) : "r"(a));
}
static __device__ __forceinline__ void ldsm4t(uint32_t& r0, uint32_t& r1, uint32_t& r2, uint32_t& r3, uint32_t a) {
    asm volatile("ldmatrix.sync.aligned.m8n8.x4.trans.shared.b16 {%0,%1,%2,%3}, [%4];"
                 : "=r"(r0), "=r"(r1), "=r"(r2), "=r"(r3) : "r"(a));
}
static __device__ __forceinline__ void mma16816f(float* c, const uint32_t* a, uint32_t b0, uint32_t b1) {
    asm volatile("mma.sync.aligned.m16n8k16.row.col.f32.f16.f16.f32 "
                 "{%0,%1,%2,%3}, {%4,%5,%6,%7}, {%8,%9}, {%0,%1,%2,%3};"
                 : "+f"(c[0]), "+f"(c[1]), "+f"(c[2]), "+f"(c[3])
                 : "r"(a[0]), "r"(a[1]), "r"(a[2]), "r"(a[3]), "r"(b0), "r"(b1));
}
static __device__ __forceinline__ void mma16816h(uint32_t* c, const uint32_t* a, uint32_t b0, uint32_t b1) {
    asm volatile("mma.sync.aligned.m16n8k16.row.col.f16.f16.f16.f16 "
                 "{%0,%1}, {%2,%3,%4,%5}, {%6,%7}, {%0,%1};"
                 : "+r"(c[0]), "+r"(c[1])
                 : "r"(a[0]), "r"(a[1]), "r"(a[2]), "r"(a[3]), "r"(b0), "r"(b1));
}
static __device__ __forceinline__ uint32_t ex2h2(uint32_t x) {
    uint32_t y; asm volatile("ex2.approx.f16x2 %0, %1;" : "=r"(y) : "r"(x)); return y;
}
static __device__ __forceinline__ uint32_t packh(float a, float b) {
    h162 t = __floats2half2_rn(a, b);
    return *reinterpret_cast<uint32_t*>(&t);
}
static __device__ __forceinline__ uint32_t hadd2u(uint32_t a, uint32_t b) {
    h162 r = __hadd2(*reinterpret_cast<h162*>(&a), *reinterpret_cast<h162*>(&b));
    return *reinterpret_cast<uint32_t*>(&r);
}
#define CP_ASYNC16(saddr, gaddr) \
    asm volatile("cp.async.cg.shared.global [%0], [%1], 16;" :: "r"(saddr), "l"(gaddr))
#define CP_COMMIT() asm volatile("cp.async.commit_group;")
#define CP_WAIT(n)  asm volatile("cp.async.wait_group %0;" :: "n"(n))

// -------------------- merged GroupNorm + weight convert --------------------
__global__ void k_gncvt(const float* __restrict__ x,
                        const float* __restrict__ sc,
                        const float* __restrict__ bi,
                        h16* __restrict__ hn,
                        const float* __restrict__ wq, const float* __restrict__ wk,
                        const float* __restrict__ wv, const float* __restrict__ wo,
                        h16* __restrict__ wout)
{
    __shared__ float red[16];
    if (blockIdx.x >= Bb * GROUPS) {
        const int bid = blockIdx.x - Bb * GROUPS;
        const int m = bid >> 8;
        const int idx = (bid & 255) * 256 + threadIdx.x;
        const float* src = (m == 0) ? wq : (m == 1) ? wk : (m == 2) ? wv : wo;
        float4 f = ((const float4*)src)[idx];
        uint2 u;
        u.x = packh(f.x, f.y);
        u.y = packh(f.z, f.w);
        ((uint2*)(wout + (size_t)m * Cc * Cc))[idx] = u;
        return;
    }

    const int bg = blockIdx.x;
    const int b = bg / GROUPS, g = bg % GROUPS;
    const size_t base = (size_t)b * CN + (size_t)g * CPG * NN;
    const float4* x4 = (const float4*)(x + base);
    h162* h2 = (h162*)(hn + base);
    const int tx = threadIdx.x;

    float s = 0.f, s2 = 0.f;
    for (int i = tx; i < 4096; i += 256) {
        float4 v = x4[i];
        s  += v.x + v.y + v.z + v.w;
        s2 += v.x*v.x + v.y*v.y + v.z*v.z + v.w*v.w;
    }
    #pragma unroll
    for (int o = 16; o; o >>= 1) {
        s  += __shfl_xor_sync(0xffffffffu, s,  o);
        s2 += __shfl_xor_sync(0xffffffffu, s2, o);
    }
    if ((tx & 31) == 0) { red[tx >> 5] = s; red[8 + (tx >> 5)] = s2; }
    __syncthreads();
    float S = 0.f, S2 = 0.f;
    #pragma unroll
    for (int i = 0; i < 8; i++) { S += red[i]; S2 += red[8 + i]; }

    const float inv_n = 1.0f / (CPG * NN);
    const float mu  = S * inv_n;
    const float var = S2 * inv_n - mu * mu;
    const float rstd = rsqrtf(var + 1e-5f);

    for (int i = tx; i < 4096; i += 256) {
        const int cg = i >> 8;
        const float a = sc[g * CPG + cg] * rstd;
        const float c0 = bi[g * CPG + cg] - mu * a;
        float4 v = x4[i];
        h2[i*2 + 0] = __floats2half2_rn(v.x * a + c0, v.y * a + c0);
        h2[i*2 + 1] = __floats2half2_rn(v.z * a + c0, v.w * a + c0);
    }
}

// -------------------- QKV projections: 128 threads, 64x128 tile, 4 CTAs/SM (R14) --------------------
#define QA_ST (64 * 72)      // A stage: [64 m][64+8 k]
#define QB_ST (64 * 136)     // B stage: [64 k][128+8 n]
#define QKV_SMEM ((2 * QA_ST + 2 * QB_ST) * (int)sizeof(h16))   // 53248 B

__global__ void __launch_bounds__(128, 4) k_qkv(
    const h16* __restrict__ wb, const h16* __restrict__ hn,
    const float* __restrict__ bq, const float* __restrict__ bk, const float* __restrict__ bv,
    h16* __restrict__ q, h16* __restrict__ k, h16* __restrict__ v)
{
    extern __shared__ h16 smp[];
    h16* As = smp;
    h16* Bs = smp + 2 * QA_ST;

    const int z = blockIdx.z;
    const int b = z / 3, w = z % 3;
    const h16* W = wb + (size_t)w * Cc * Cc;
    const float* bias = (w == 0) ? bq : (w == 1) ? bk : bv;
    h16* Y = ((w == 0) ? q : (w == 1) ? k : v) + (size_t)b * CN;
    const h16* X = hn + (size_t)b * CN;
    const float oscale = (w == 0) ? 0.18033688011112042f : 1.0f;
    const int m0 = blockIdx.y * 64, n0 = blockIdx.x * 128;

    const int tid = threadIdx.x;
    const int lane = tid & 31;
    const int wn = tid >> 5;

    auto load_stage = [&](int s, int buf) {
        const h16* Wg = W + (size_t)m0 * Cc + s * 64;
        h16* Ab = As + buf * QA_ST;
        #pragma unroll
        for (int j = 0; j < 4; j++) {
            int idx = tid + j * 128;
            int row = idx >> 3, c8 = (idx & 7) * 8;
            CP_ASYNC16(smem_u32(Ab + row * 72 + c8), Wg + (size_t)row * Cc + c8);
        }
        const h16* Xg = X + (size_t)(s * 64) * NN + n0;
        h16* Bbp = Bs + buf * QB_ST;
        #pragma unroll
        for (int j = 0; j < 8; j++) {
            int idx = tid + j * 128;
            int row = idx >> 4, c8 = (idx & 15) * 8;
            CP_ASYNC16(smem_u32(Bbp + row * 136 + c8), Xg + (size_t)row * NN + c8);
        }
    };

    load_stage(0, 0);
    CP_COMMIT();

    const int arow = lane & 15;
    const int acolh = (lane >> 4) * 8;
    const int brow = ((lane >> 3) & 1) * 8 + (lane & 7);
    const int bcolh = (lane >> 4) * 8;

    float acc[4][4][4] = {};

    #pragma unroll 1
    for (int s = 0; s < 8; s++) {
        CP_WAIT(0);
        __syncthreads();
        if (s + 1 < 8) { load_stage(s + 1, (s + 1) & 1); CP_COMMIT(); }
        const h16* Ab = As + (s & 1) * QA_ST;
        const h16* Bbp = Bs + (s & 1) * QB_ST;
        #pragma unroll
        for (int k16 = 0; k16 < 4; k16++) {
            uint32_t a[4][4], bb[2][4];
            #pragma unroll
            for (int mt = 0; mt < 4; mt++)
                ldsm4(a[mt][0], a[mt][1], a[mt][2], a[mt][3],
                      smem_u32(Ab + (mt * 16 + arow) * 72 + k16 * 16 + acolh));
            #pragma unroll
            for (int bt = 0; bt < 2; bt++)
                ldsm4t(bb[bt][0], bb[bt][1], bb[bt][2], bb[bt][3],
                       smem_u32(Bbp + (k16 * 16 + brow) * 136 + wn * 32 + bt * 16 + bcolh));
            #pragma unroll
            for (int mt = 0; mt < 4; mt++)
                #pragma unroll
                for (int ni = 0; ni < 4; ni++)
                    mma16816f(acc[mt][ni], a[mt], bb[ni >> 1][(ni & 1) * 2], bb[ni >> 1][(ni & 1) * 2 + 1]);
        }
    }

    #pragma unroll
    for (int mt = 0; mt < 4; mt++) {
        const int row = m0 + mt * 16 + (lane >> 2);
        const float b0v = bias[row], b1v = bias[row + 8];
        #pragma unroll
        for (int ni = 0; ni < 4; ni++) {
            const int col = n0 + wn * 32 + ni * 8 + ((lane & 3) << 1);
            *(h162*)(Y + (size_t)row * NN + col) =
                __floats2half2_rn((acc[mt][ni][0] + b0v) * oscale,
                                  (acc[mt][ni][1] + b0v) * oscale);
            *(h162*)(Y + (size_t)(row + 8) * NN + col) =
                __floats2half2_rn((acc[mt][ni][2] + b1v) * oscale,
                                  (acc[mt][ni][3] + b1v) * oscale);
        }
    }
}

// -------------------- fused flash attention: 64-q CTA, KV 64-wide, 4 CTAs/SM --------------------
// R8-proven inner pipeline (mt=1, KV64, f16 S-acc, in-place ex2, scalar l) at
// DOUBLE warp occupancy: 128 threads x 4 CTAs/SM = 16 warps/SM.
#define AQPAD 72
#define AQT_E (64 * AQPAD)      // Q tile: [64 d][64 q + pad]
#define AKPAD 72
#define AKT_E (64 * AKPAD)      // KV tile: [64 d][64 k + pad]
#define ATTN_SMEM ((AQT_E + 4 * AKT_E) * (int)sizeof(h16))   // 46080 B

__global__ void __launch_bounds__(128, 4) k_attn(
    const h16* __restrict__ Q, const h16* __restrict__ K,
    const h16* __restrict__ V, h16* __restrict__ OQ)
{
    extern __shared__ h16 sm[];
    h16* Qs = sm;                         // [64][72]
    h16* Ks = sm + AQT_E;                 // 2 bufs [64][72]
    h16* Vs = sm + AQT_E + 2 * AKT_E;     // 2 bufs

    const int bh = blockIdx.y;
    const int b = bh >> 3, h = bh & 7;
    const size_t hb = ((size_t)b * Cc + h * DD) * NN;
    const h16* Qg = Q + hb;
    const h16* Kg = K + hb;
    const h16* Vg = V + hb;
    const int q0 = blockIdx.x * 64;

    const int tid = threadIdx.x;           // 0..127
    const int lane = tid & 31;
    const int warp = tid >> 5;              // 0..3, owns 16 q-rows

    // ---- load Q tile (64 d x 64 q) ----
    #pragma unroll
    for (int j = 0; j < 4; j++) {
        int idx = tid + j * 128;
        int row = idx >> 3, c8 = (idx & 7) * 8;
        CP_ASYNC16(smem_u32(&Qs[row * AQPAD + c8]), Qg + (size_t)row * NN + q0 + c8);
    }
    CP_COMMIT();

    auto load_kv = [&](int kt, int buf) {
        const int k0 = kt * 64;
        #pragma unroll
        for (int j = 0; j < 4; j++) {
            int idx = tid + j * 128;
            int row = idx >> 3, c8 = (idx & 7) * 8;
            CP_ASYNC16(smem_u32(&Ks[buf * AKT_E + row * AKPAD + c8]),
                       Kg + (size_t)row * NN + k0 + c8);
            CP_ASYNC16(smem_u32(&Vs[buf * AKT_E + row * AKPAD + c8]),
                       Vg + (size_t)row * NN + k0 + c8);
        }
    };

    load_kv(0, 0);
    CP_COMMIT();

    CP_WAIT(1);           // Q done (kv0 may still be in flight)
    __syncthreads();

    // ---- Q fragments: one A tile [16 q][64 d] per warp ----
    uint32_t qf[4][4];
    {
        const int t_arow = (lane >> 4) * 8 + (lane & 7);
        const int t_acol = ((lane >> 3) & 1) * 8;
        #pragma unroll
        for (int d16 = 0; d16 < 4; d16++)
            ldsm4t(qf[d16][0], qf[d16][1], qf[d16][2], qf[d16][3],
                   smem_u32(&Qs[(d16 * 16 + t_arow) * AQPAD + warp * 16 + t_acol]));
    }

    float lf0 = 0.f, lf1 = 0.f;
    float oacc[8][4] = {};

    const int t_brow = ((lane >> 3) & 1) * 8 + (lane & 7);   // S-phase B (trans)
    const int t_bcol = (lane >> 4) * 8;
    const int vrow = ((lane >> 4) & 1) * 8 + (lane & 7);     // PV-phase B (non-trans)
    const int vcol = ((lane >> 3) & 1) * 8;

    #pragma unroll 1
    for (int kt = 0; kt < 16; kt++) {
        CP_WAIT(0);
        __syncthreads();
        if (kt + 1 < 16) { load_kv(kt + 1, (kt + 1) & 1); CP_COMMIT(); }

        const h16* Kb = Ks + (kt & 1) * AKT_E;
        const h16* Vb = Vs + (kt & 1) * AKT_E;

        // ---- S = Q^T K  (m=16 q, n=64 k); f16 accumulator ----
        uint32_t sacc[8][2] = {};
        #pragma unroll
        for (int d16 = 0; d16 < 4; d16++) {
            #pragma unroll
            for (int nt = 0; nt < 4; nt++) {
                uint32_t bb[4];
                ldsm4t(bb[0], bb[1], bb[2], bb[3],
                       smem_u32(&Kb[(d16 * 16 + t_brow) * AKPAD + nt * 16 + t_bcol]));
                mma16816h(sacc[2 * nt],     qf[d16], bb[0], bb[1]);
                mma16816h(sacc[2 * nt + 1], qf[d16], bb[2], bb[3]);
            }
        }

        // ---- per k16 chunk: in-place ex2, scalar l partials, PV-mma ----
        #pragma unroll
        for (int t = 0; t < 4; t++) {
            uint32_t pf[4];
            pf[0] = ex2h2(sacc[2 * t][0]);
            pf[1] = ex2h2(sacc[2 * t][1]);
            pf[2] = ex2h2(sacc[2 * t + 1][0]);
            pf[3] = ex2h2(sacc[2 * t + 1][1]);

            uint32_t s0 = hadd2u(pf[0], pf[2]);
            uint32_t s1 = hadd2u(pf[1], pf[3]);
            float2 f0 = __half22float2(*reinterpret_cast<h162*>(&s0));
            float2 f1 = __half22float2(*reinterpret_cast<h162*>(&s1));
            lf0 += f0.x + f0.y;
            lf1 += f1.x + f1.y;

            #pragma unroll
            for (int nt = 0; nt < 4; nt++) {
                uint32_t bb[4];
                ldsm4(bb[0], bb[1], bb[2], bb[3],
                      smem_u32(&Vb[(nt * 16 + vrow) * AKPAD + t * 16 + vcol]));
                mma16816f(oacc[2 * nt],     pf, bb[0], bb[1]);
                mma16816f(oacc[2 * nt + 1], pf, bb[2], bb[3]);
            }
        }
    }

    // ---- epilogue: quad-reduce l, normalize, store to [b][q][c] ----
    lf0 += __shfl_xor_sync(0xffffffffu, lf0, 1);
    lf0 += __shfl_xor_sync(0xffffffffu, lf0, 2);
    lf1 += __shfl_xor_sync(0xffffffffu, lf1, 1);
    lf1 += __shfl_xor_sync(0xffffffffu, lf1, 2);
    const float inv0 = 1.0f / lf0;
    const float inv1 = 1.0f / lf1;

    const int qrow = q0 + warp * 16 + (lane >> 2);
    h16* p0 = OQ + ((size_t)b * NN + qrow) * Cc + h * DD + ((lane & 3) << 1);
    h16* p1 = p0 + (size_t)8 * Cc;
    #pragma unroll
    for (int j = 0; j < 8; j++) {
        *(h162*)(p0 + j * 8) = __floats2half2_rn(oacc[j][0] * inv0, oacc[j][1] * inv0);
        *(h162*)(p1 + j * 8) = __floats2half2_rn(oacc[j][2] * inv1, oacc[j][3] * inv1);
    }
}

// -------------------- out-projection: 128 threads, 64x128 tile, 4 CTAs/SM (R14) --------------------
#define OB_ST (128 * 72)
#define OPROJ_SMEM ((2 * QA_ST + 2 * OB_ST) * (int)sizeof(h16))   // 55296 B

__global__ void __launch_bounds__(128, 4) k_oproj(
    const h16* __restrict__ wb, const h16* __restrict__ ohq,
    const float* __restrict__ bo, const float* __restrict__ xres,
    float* __restrict__ out)
{
    extern __shared__ h16 smo[];
    h16* As = smo;
    h16* Bs = smo + 2 * QA_ST;

    const int b = blockIdx.z;
    const h16* W = wb + (size_t)3 * Cc * Cc;
    const h16* Xq = ohq + (size_t)b * NN * Cc;
    const float* R = xres + (size_t)b * CN;
    float* Y = out + (size_t)b * CN;
    const int m0 = blockIdx.y * 64, n0 = blockIdx.x * 128;

    const int tid = threadIdx.x;
    const int lane = tid & 31;
    const int wn = tid >> 5;

    auto load_stage = [&](int s, int buf) {
        h16* Ab = As + buf * QA_ST;
        h16* Bbp = Bs + buf * OB_ST;
        #pragma unroll
        for (int j = 0; j < 4; j++) {
            int idx = tid + j * 128;
            int row = idx >> 3, c8 = (idx & 7) * 8;
            CP_ASYNC16(smem_u32(Ab + row * 72 + c8),
                       W + (size_t)(m0 + row) * Cc + s * 64 + c8);
        }
        #pragma unroll
        for (int j = 0; j < 8; j++) {
            int idx = tid + j * 128;
            int row = idx >> 3, c8 = (idx & 7) * 8;
            CP_ASYNC16(smem_u32(Bbp + row * 72 + c8),
                       Xq + (size_t)(n0 + row) * Cc + s * 64 + c8);
        }
    };

    load_stage(0, 0);
    CP_COMMIT();

    const int arow = lane & 15;
    const int acolh = (lane >> 4) * 8;
    const int brow = ((lane >> 4) & 1) * 8 + (lane & 7);
    const int bcol = ((lane >> 3) & 1) * 8;

    float acc[4][4][4] = {};

    #pragma unroll 1
    for (int s = 0; s < 8; s++) {
        CP_WAIT(0);
        __syncthreads();
        if (s + 1 < 8) { load_stage(s + 1, (s + 1) & 1); CP_COMMIT(); }
        const h16* Ab = As + (s & 1) * QA_ST;
        const h16* Bbp = Bs + (s & 1) * OB_ST;
        #pragma unroll
        for (int k16 = 0; k16 < 4; k16++) {
            uint32_t a[4][4], bb[2][4];
            #pragma unroll
            for (int mt = 0; mt < 4; mt++)
                ldsm4(a[mt][0], a[mt][1], a[mt][2], a[mt][3],
                      smem_u32(Ab + (mt * 16 + arow) * 72 + k16 * 16 + acolh));
            #pragma unroll
            for (int nt = 0; nt < 2; nt++)
                ldsm4(bb[nt][0], bb[nt][1], bb[nt][2], bb[nt][3],
                      smem_u32(Bbp + (wn * 32 + nt * 16 + brow) * 72 + k16 * 16 + bcol));
            #pragma unroll
            for (int mt = 0; mt < 4; mt++)
                #pragma unroll
                for (int ni = 0; ni < 4; ni++)
                    mma16816f(acc[mt][ni], a[mt], bb[ni >> 1][(ni & 1) * 2], bb[ni >> 1][(ni & 1) * 2 + 1]);
        }
    }

    #pragma unroll
    for (int mt = 0; mt < 4; mt++) {
        const int row = m0 + mt * 16 + (lane >> 2);
        const float b0v = bo[row], b1v = bo[row + 8];
        #pragma unroll
        for (int ni = 0; ni < 4; ni++) {
            const int col = n0 + wn * 32 + ni * 8 + ((lane & 3) << 1);
            float2 r0 = *(const float2*)(R + (size_t)row * NN + col);
            float2 r1 = *(const float2*)(R + (size_t)(row + 8) * NN + col);
            float2 o0, o1;
            o0.x = acc[mt][ni][0] + b0v + r0.x;
            o0.y = acc[mt][ni][1] + b0v + r0.y;
            o1.x = acc[mt][ni][2] + b1v + r1.x;
            o1.y = acc[mt][ni][3] + b1v + r1.y;
            *(float2*)(Y + (size_t)row * NN + col) = o0;
            *(float2*)(Y + (size_t)(row + 8) * NN + col) = o1;
        }
    }
}

// -------------------- launch (single stream; multi-stream is banned by the harness) --------------------
extern "C" void kernel_launch(void* const* d_in, const int* in_sizes, int n_in,
                              void* d_out, int out_size)
{
    const float* x        = (const float*)d_in[0];
    const float* gn_scale = (const float*)d_in[1];
    const float* gn_bias  = (const float*)d_in[2];
    const float* wq = (const float*)d_in[3];
    const float* bq = (const float*)d_in[4];
    const float* wk = (const float*)d_in[5];
    const float* bk = (const float*)d_in[6];
    const float* wv = (const float*)d_in[7];
    const float* bv = (const float*)d_in[8];
    const float* wo = (const float*)d_in[9];
    const float* bo = (const float*)d_in[10];
    float* out = (float*)d_out;

    h16 *hn, *q, *k, *v, *oh, *wb;
    cudaGetSymbolAddress((void**)&hn, g_hnb);
    cudaGetSymbolAddress((void**)&q,  g_qb);
    cudaGetSymbolAddress((void**)&k,  g_kb);
    cudaGetSymbolAddress((void**)&v,  g_vb);
    cudaGetSymbolAddress((void**)&oh, g_ohb);
    cudaGetSymbolAddress((void**)&wb, g_wb);

    static int attrs_set = 0;
    if (!attrs_set) {
        cudaFuncSetAttribute(k_attn,  cudaFuncAttributeMaxDynamicSharedMemorySize, ATTN_SMEM);
        cudaFuncSetAttribute(k_qkv,   cudaFuncAttributeMaxDynamicSharedMemorySize, QKV_SMEM);
        cudaFuncSetAttribute(k_oproj, cudaFuncAttributeMaxDynamicSharedMemorySize, OPROJ_SMEM);
        attrs_set = 1;
    }

    // 1. GroupNorm -> fp16 (+ weight convert, merged)
    k_gncvt<<<Bb * GROUPS + 1024, 256>>>(x, gn_scale, gn_bias, hn, wq, wk, wv, wo, wb);

    // 2. Q/K/V projections (Q pre-scaled by 0.125*log2 e)
    k_qkv<<<dim3(NN / 128, Cc / 64, Bb * 3), 128, QKV_SMEM>>>(wb, hn, bq, bk, bv, q, k, v);

    // 3. fused attention: 64-q CTAs, KV 64-wide, 4 CTAs/SM (16 warps/SM)
    k_attn<<<dim3(NN / 64, Bb * HEADS), 128, ATTN_SMEM>>>(q, k, v, oh);

    // 4. out = wo * oh + bo + x
    k_oproj<<<dim3(NN / 128, Cc / 64, Bb), 128, OPROJ_SMEM>>>(wb, oh, bo, x, out);
}

// round 17
// speedup vs baseline: 1.1452x; 1.0874x over previous
#include <cuda_runtime.h>
#include <cuda_fp16.h>
#include <math.h>
#include <stdint.h>

#define Bb 8
#define Cc 512
#define NN 1024
#define HEADS 8
#define DD 64
#define GROUPS 32
#define CPG (Cc / GROUPS)   // 16
#define CN ((size_t)Cc * NN)

typedef __half h16;
typedef __half2 h162;

// -------------------- scratch (device globals) --------------------
static __device__ h16 g_hnb[(size_t)Bb * Cc * NN];   // TILED: [b][nt(8)][ks(8)][sub(2)][64c x 64n] SW128
static __device__ h16 g_qb [(size_t)Bb * Cc * NN];   // [c][n] (attn input, unchanged)
static __device__ h16 g_kb [(size_t)Bb * Cc * NN];
static __device__ h16 g_vb [(size_t)Bb * Cc * NN];
static __device__ h16 g_ohb[(size_t)Bb * NN * Cc];   // TILED: [b][qt(8)][cs(8)][128q x 64c] SW128
static __device__ h16 g_wb [(size_t)4 * Cc * Cc];    // TILED: [w][mt(8)][ks(8)][64m x 64k] SW128

// -------------------- PTX helpers --------------------
static __device__ __forceinline__ uint32_t smem_u32(const void* p) {
    return (uint32_t)__cvta_generic_to_shared(p);
}
static __device__ __forceinline__ uint32_t sw128(uint32_t o) { return o ^ ((o >> 3) & 0x70); }
static __device__ __forceinline__ void ldsm4(uint32_t& r0, uint32_t& r1, uint32_t& r2, uint32_t& r3, uint32_t a) {
    asm volatile("ldmatrix.sync.aligned.m8n8.x4.shared.b16 {%0,%1,%2,%3}, [%4];"
                 : "=r"(r0), "=r"(r1), "=r"(r2), "=r"(r3) : "r"(a));
}
static __device__ __forceinline__ void ldsm4t(uint32_t& r0, uint32_t& r1, uint32_t& r2, uint32_t& r3, uint32_t a) {
    asm volatile("ldmatrix.sync.aligned.m8n8.x4.trans.shared.b16 {%0,%1,%2,%3}, [%4];"
                 : "=r"(r0), "=r"(r1), "=r"(r2), "=r"(r3) : "r"(a));
}
static __device__ __forceinline__ void mma16816f(float* c, const uint32_t* a, uint32_t b0, uint32_t b1) {
    asm volatile("mma.sync.aligned.m16n8k16.row.col.f32.f16.f16.f32 "
                 "{%0,%1,%2,%3}, {%4,%5,%6,%7}, {%8,%9}, {%0,%1,%2,%3};"
                 : "+f"(c[0]), "+f"(c[1]), "+f"(c[2]), "+f"(c[3])
                 : "r"(a[0]), "r"(a[1]), "r"(a[2]), "r"(a[3]), "r"(b0), "r"(b1));
}
static __device__ __forceinline__ void mma16816h(uint32_t* c, const uint32_t* a, uint32_t b0, uint32_t b1) {
    asm volatile("mma.sync.aligned.m16n8k16.row.col.f16.f16.f16.f16 "
                 "{%0,%1}, {%2,%3,%4,%5}, {%6,%7}, {%0,%1};"
                 : "+r"(c[0]), "+r"(c[1])
                 : "r"(a[0]), "r"(a[1]), "r"(a[2]), "r"(a[3]), "r"(b0), "r"(b1));
}
static __device__ __forceinline__ uint32_t ex2h2(uint32_t x) {
    uint32_t y; asm volatile("ex2.approx.f16x2 %0, %1;" : "=r"(y) : "r"(x)); return y;
}
static __device__ __forceinline__ uint32_t packh(float a, float b) {
    h162 t = __floats2half2_rn(a, b);
    return *reinterpret_cast<uint32_t*>(&t);
}
static __device__ __forceinline__ uint32_t hadd2u(uint32_t a, uint32_t b) {
    h162 r = __hadd2(*reinterpret_cast<h162*>(&a), *reinterpret_cast<h162*>(&b));
    return *reinterpret_cast<uint32_t*>(&r);
}
#define CP_ASYNC16(saddr, gaddr) \
    asm volatile("cp.async.cg.shared.global [%0], [%1], 16;" :: "r"(saddr), "l"(gaddr))
#define CP_COMMIT() asm volatile("cp.async.commit_group;")
#define CP_WAIT(n)  asm volatile("cp.async.wait_group %0;" :: "n"(n))

// ---- mbarrier + bulk copy (mbarrier forms compile-proven on sm_103 in R7) ----
#define MBAR_INIT(a, cnt) \
    asm volatile("mbarrier.init.shared.b64 [%0], %1;" :: "r"((uint32_t)(a)), "r"((uint32_t)(cnt)) : "memory")
#define MBAR_EXPECT(a, n) \
    asm volatile("mbarrier.arrive.expect_tx.shared.b64 _, [%0], %1;" :: "r"((uint32_t)(a)), "r"((uint32_t)(n)) : "memory")
#define MBAR_WAIT(a, par) do { \
    uint32_t _m = (uint32_t)(a), _p = (uint32_t)(par); \
    asm volatile("{\n\t.reg .pred P1;\n\t" \
        "WAIT_LOOP_%=:\n\t" \
        "mbarrier.try_wait.parity.acquire.cta.shared::cta.b64 P1, [%0], %1, 0x989680;\n\t" \
        "@P1 bra.uni WAIT_DONE_%=;\n\t" \
        "bra.uni WAIT_LOOP_%=;\n\t" \
        "WAIT_DONE_%=:\n\t}" :: "r"(_m), "r"(_p) : "memory"); \
} while (0)
#define CP_BULK(dst, src, bytes, mbar) \
    asm volatile("cp.async.bulk.shared::cluster.global.mbarrier::complete_tx::bytes [%0], [%1], %2, [%3];" \
        :: "r"((uint32_t)(dst)), "l"(src), "r"((uint32_t)(bytes)), "r"((uint32_t)(mbar)) : "memory")

// -------------------- merged GroupNorm + weight convert (TILED outputs) --------------------
__global__ void k_gncvt(const float* __restrict__ x,
                        const float* __restrict__ sc,
                        const float* __restrict__ bi,
                        h16* __restrict__ hn,
                        const float* __restrict__ wq, const float* __restrict__ wk,
                        const float* __restrict__ wv, const float* __restrict__ wo,
                        h16* __restrict__ wout)
{
    __shared__ float red[16];
    if (blockIdx.x >= Bb * GROUPS) {
        // weight convert into tiled+swizzled layout: [w][mt][ks][64m x 64k]
        const int bid = blockIdx.x - Bb * GROUPS;
        const int m = bid >> 8;
        const int idx = (bid & 255) * 256 + threadIdx.x;   // quad index
        const int o  = idx >> 7;                           // output row 0..511
        const int c4 = (idx & 127) * 4;                    // k col 0..508
        const float* src = (m == 0) ? wq : (m == 1) ? wk : (m == 2) ? wv : wo;
        float4 f = ((const float4*)src)[idx];
        uint2 u;
        u.x = packh(f.x, f.y);
        u.y = packh(f.z, f.w);
        const int mt = o >> 6, ks = c4 >> 6;
        size_t base = (((size_t)m * 8 + mt) * 8 + ks) * 8192;
        uint32_t local = (uint32_t)((o & 63) * 128 + (c4 & 63) * 2);
        *(uint2*)((char*)wout + base + sw128(local)) = u;
        return;
    }

    const int bg = blockIdx.x;
    const int b = bg / GROUPS, g = bg % GROUPS;
    const size_t xbase = (size_t)b * CN + (size_t)g * CPG * NN;
    const float4* x4 = (const float4*)(x + xbase);
    const int tx = threadIdx.x;

    float s = 0.f, s2 = 0.f;
    for (int i = tx; i < 4096; i += 256) {
        float4 v = x4[i];
        s  += v.x + v.y + v.z + v.w;
        s2 += v.x*v.x + v.y*v.y + v.z*v.z + v.w*v.w;
    }
    #pragma unroll
    for (int o = 16; o; o >>= 1) {
        s  += __shfl_xor_sync(0xffffffffu, s,  o);
        s2 += __shfl_xor_sync(0xffffffffu, s2, o);
    }
    if ((tx & 31) == 0) { red[tx >> 5] = s; red[8 + (tx >> 5)] = s2; }
    __syncthreads();
    float S = 0.f, S2 = 0.f;
    #pragma unroll
    for (int i = 0; i < 8; i++) { S += red[i]; S2 += red[8 + i]; }

    const float inv_n = 1.0f / (CPG * NN);
    const float mu  = S * inv_n;
    const float var = S2 * inv_n - mu * mu;
    const float rstd = rsqrtf(var + 1e-5f);

    // write hn into tiled layout: [b][nt][ks][sub][64c x 64n] SW128
    for (int i = tx; i < 4096; i += 256) {
        const int cg = i >> 8;                 // channel within group
        const int n4 = (i & 255) * 4;          // n position (quad)
        const int c = g * CPG + cg;            // global channel
        const float a = sc[c] * rstd;
        const float c0 = bi[c] - mu * a;
        float4 v = x4[i];
        uint2 u;
        u.x = packh(v.x * a + c0, v.y * a + c0);
        u.y = packh(v.z * a + c0, v.w * a + c0);
        const int nt = n4 >> 7, sub = (n4 >> 6) & 1, ks = c >> 6;
        size_t base = (((size_t)b * 8 + nt) * 8 + ks) * 16384 + (size_t)sub * 8192;
        uint32_t local = (uint32_t)((c & 63) * 128 + (n4 & 63) * 2);
        *(uint2*)((char*)hn + base + sw128(local)) = u;
    }
}

// -------------------- QKV projections: bulk-copy staged, 128 thr, 4 CTAs/SM --------------------
#define QKV_SMEM (2 * 24576)    // 2 stages x (A 8KB + B 16KB)

__global__ void __launch_bounds__(128, 4) k_qkv(
    const h16* __restrict__ wbt, const h16* __restrict__ hnt,
    const float* __restrict__ bq, const float* __restrict__ bk, const float* __restrict__ bv,
    h16* __restrict__ q, h16* __restrict__ k, h16* __restrict__ v)
{
    extern __shared__ char smq[];
    __shared__ uint64_t mbar[2];
    const uint32_t sb = smem_u32(smq);
    const uint32_t mb0 = smem_u32(&mbar[0]);
    const uint32_t mb1 = smem_u32(&mbar[1]);

    const int z = blockIdx.z;
    const int b = z / 3, w = z % 3;
    const float* bias = (w == 0) ? bq : (w == 1) ? bk : bv;
    h16* Y = ((w == 0) ? q : (w == 1) ? k : v) + (size_t)b * CN;
    const float oscale = (w == 0) ? 0.18033688011112042f : 1.0f;
    const int mt = blockIdx.y, ntile = blockIdx.x;
    const int m0 = mt * 64, n0 = ntile * 128;

    const char* Asrc = (const char*)wbt + ((size_t)w * 8 + mt) * 8 * 8192;
    const char* Bsrc = (const char*)hnt + ((size_t)b * 8 + ntile) * 8 * 16384;

    const int tid = threadIdx.x;
    const int lane = tid & 31;
    const int wn = tid >> 5;

    if (tid == 0) { MBAR_INIT(mb0, 1); MBAR_INIT(mb1, 1); }
    __syncthreads();
    if (tid == 0) {
        MBAR_EXPECT(mb0, 24576);
        CP_BULK(sb,        Asrc, 8192,  mb0);
        CP_BULK(sb + 8192, Bsrc, 16384, mb0);
    }

    const uint32_t a_off = (uint32_t)((lane & 15) * 128 + (lane >> 4) * 16);
    const int brow = ((lane >> 3) & 1) * 8 + (lane & 7);

    float acc[4][4][4] = {};
    int ph0 = 0, ph1 = 0;

    #pragma unroll 1
    for (int s = 0; s < 8; s++) {
        if (s & 1) { MBAR_WAIT(mb1, ph1); ph1 ^= 1; }
        else       { MBAR_WAIT(mb0, ph0); ph0 ^= 1; }
        __syncthreads();
        if (s + 1 < 8 && tid == 0) {
            const uint32_t mn = ((s + 1) & 1) ? mb1 : mb0;
            const uint32_t dst = sb + ((s + 1) & 1) * 24576;
            MBAR_EXPECT(mn, 24576);
            CP_BULK(dst,        Asrc + (size_t)(s + 1) * 8192,  8192,  mn);
            CP_BULK(dst + 8192, Bsrc + (size_t)(s + 1) * 16384, 16384, mn);
        }
        const uint32_t Ab = sb + (s & 1) * 24576;
        const uint32_t Bbs = Ab + 8192;
        #pragma unroll
        for (int k16 = 0; k16 < 4; k16++) {
            uint32_t a[4][4], bb[2][4];
            #pragma unroll
            for (int mt2 = 0; mt2 < 4; mt2++)
                ldsm4(a[mt2][0], a[mt2][1], a[mt2][2], a[mt2][3],
                      Ab + sw128((uint32_t)(mt2 * 16) * 128 + a_off + k16 * 32));
            #pragma unroll
            for (int bt = 0; bt < 2; bt++) {
                const uint32_t no = (uint32_t)(wn * 32 + bt * 16 + (lane >> 4) * 8);
                ldsm4t(bb[bt][0], bb[bt][1], bb[bt][2], bb[bt][3],
                       Bbs + (no >> 6) * 8192 +
                       sw128((uint32_t)(k16 * 16 + brow) * 128 + (no & 63) * 2));
            }
            #pragma unroll
            for (int mt2 = 0; mt2 < 4; mt2++)
                #pragma unroll
                for (int ni = 0; ni < 4; ni++)
                    mma16816f(acc[mt2][ni], a[mt2], bb[ni >> 1][(ni & 1) * 2], bb[ni >> 1][(ni & 1) * 2 + 1]);
        }
    }

    #pragma unroll
    for (int mt2 = 0; mt2 < 4; mt2++) {
        const int row = m0 + mt2 * 16 + (lane >> 2);
        const float b0v = bias[row], b1v = bias[row + 8];
        #pragma unroll
        for (int ni = 0; ni < 4; ni++) {
            const int col = n0 + wn * 32 + ni * 8 + ((lane & 3) << 1);
            *(h162*)(Y + (size_t)row * NN + col) =
                __floats2half2_rn((acc[mt2][ni][0] + b0v) * oscale,
                                  (acc[mt2][ni][1] + b0v) * oscale);
            *(h162*)(Y + (size_t)(row + 8) * NN + col) =
                __floats2half2_rn((acc[mt2][ni][2] + b1v) * oscale,
                                  (acc[mt2][ni][3] + b1v) * oscale);
        }
    }
}

// -------------------- fused flash attention (R16 mainloop; tiled epilogue) --------------------
#define AQPAD 72
#define AQT_E (64 * AQPAD)
#define AKPAD 72
#define AKT_E (64 * AKPAD)
#define ATTN_SMEM ((AQT_E + 4 * AKT_E) * (int)sizeof(h16))   // 46080 B

__global__ void __launch_bounds__(128, 4) k_attn(
    const h16* __restrict__ Q, const h16* __restrict__ K,
    const h16* __restrict__ V, h16* __restrict__ OQ)
{
    extern __shared__ h16 sm[];
    h16* Qs = sm;
    h16* Ks = sm + AQT_E;
    h16* Vs = sm + AQT_E + 2 * AKT_E;

    const int bh = blockIdx.y;
    const int b = bh >> 3, h = bh & 7;
    const size_t hb = ((size_t)b * Cc + h * DD) * NN;
    const h16* Qg = Q + hb;
    const h16* Kg = K + hb;
    const h16* Vg = V + hb;
    const int q0 = blockIdx.x * 64;

    const int tid = threadIdx.x;
    const int lane = tid & 31;
    const int warp = tid >> 5;

    #pragma unroll
    for (int j = 0; j < 4; j++) {
        int idx = tid + j * 128;
        int row = idx >> 3, c8 = (idx & 7) * 8;
        CP_ASYNC16(smem_u32(&Qs[row * AQPAD + c8]), Qg + (size_t)row * NN + q0 + c8);
    }
    CP_COMMIT();

    auto load_kv = [&](int kt, int buf) {
        const int k0 = kt * 64;
        #pragma unroll
        for (int j = 0; j < 4; j++) {
            int idx = tid + j * 128;
            int row = idx >> 3, c8 = (idx & 7) * 8;
            CP_ASYNC16(smem_u32(&Ks[buf * AKT_E + row * AKPAD + c8]),
                       Kg + (size_t)row * NN + k0 + c8);
            CP_ASYNC16(smem_u32(&Vs[buf * AKT_E + row * AKPAD + c8]),
                       Vg + (size_t)row * NN + k0 + c8);
        }
    };

    load_kv(0, 0);
    CP_COMMIT();

    CP_WAIT(1);
    __syncthreads();

    uint32_t qf[4][4];
    {
        const int t_arow = (lane >> 4) * 8 + (lane & 7);
        const int t_acol = ((lane >> 3) & 1) * 8;
        #pragma unroll
        for (int d16 = 0; d16 < 4; d16++)
            ldsm4t(qf[d16][0], qf[d16][1], qf[d16][2], qf[d16][3],
                   smem_u32(&Qs[(d16 * 16 + t_arow) * AQPAD + warp * 16 + t_acol]));
    }

    float lf0 = 0.f, lf1 = 0.f;
    float oacc[8][4] = {};

    const int t_brow = ((lane >> 3) & 1) * 8 + (lane & 7);
    const int t_bcol = (lane >> 4) * 8;
    const int vrow = ((lane >> 4) & 1) * 8 + (lane & 7);
    const int vcol = ((lane >> 3) & 1) * 8;

    #pragma unroll 1
    for (int kt = 0; kt < 16; kt++) {
        CP_WAIT(0);
        __syncthreads();
        if (kt + 1 < 16) { load_kv(kt + 1, (kt + 1) & 1); CP_COMMIT(); }

        const h16* Kb = Ks + (kt & 1) * AKT_E;
        const h16* Vb = Vs + (kt & 1) * AKT_E;

        uint32_t sacc[8][2] = {};
        #pragma unroll
        for (int d16 = 0; d16 < 4; d16++) {
            #pragma unroll
            for (int nt = 0; nt < 4; nt++) {
                uint32_t bb[4];
                ldsm4t(bb[0], bb[1], bb[2], bb[3],
                       smem_u32(&Kb[(d16 * 16 + t_brow) * AKPAD + nt * 16 + t_bcol]));
                mma16816h(sacc[2 * nt],     qf[d16], bb[0], bb[1]);
                mma16816h(sacc[2 * nt + 1], qf[d16], bb[2], bb[3]);
            }
        }

        #pragma unroll
        for (int t = 0; t < 4; t++) {
            uint32_t pf[4];
            pf[0] = ex2h2(sacc[2 * t][0]);
            pf[1] = ex2h2(sacc[2 * t][1]);
            pf[2] = ex2h2(sacc[2 * t + 1][0]);
            pf[3] = ex2h2(sacc[2 * t + 1][1]);

            uint32_t s0 = hadd2u(pf[0], pf[2]);
            uint32_t s1 = hadd2u(pf[1], pf[3]);
            float2 f0 = __half22float2(*reinterpret_cast<h162*>(&s0));
            float2 f1 = __half22float2(*reinterpret_cast<h162*>(&s1));
            lf0 += f0.x + f0.y;
            lf1 += f1.x + f1.y;

            #pragma unroll
            for (int nt = 0; nt < 4; nt++) {
                uint32_t bb[4];
                ldsm4(bb[0], bb[1], bb[2], bb[3],
                      smem_u32(&Vb[(nt * 16 + vrow) * AKPAD + t * 16 + vcol]));
                mma16816f(oacc[2 * nt],     pf, bb[0], bb[1]);
                mma16816f(oacc[2 * nt + 1], pf, bb[2], bb[3]);
            }
        }
    }

    lf0 += __shfl_xor_sync(0xffffffffu, lf0, 1);
    lf0 += __shfl_xor_sync(0xffffffffu, lf0, 2);
    lf1 += __shfl_xor_sync(0xffffffffu, lf1, 1);
    lf1 += __shfl_xor_sync(0xffffffffu, lf1, 2);
    const float inv0 = 1.0f / lf0;
    const float inv1 = 1.0f / lf1;

    // epilogue into TILED ohq: [b][qt][cs=h][128q x 64c] SW128
    const int qrow = q0 + warp * 16 + (lane >> 2);
    const int qt = qrow >> 7;
    char* tb = (char*)OQ + (((size_t)b * 8 + qt) * 8 + h) * 16384;
    #pragma unroll
    for (int j = 0; j < 8; j++) {
        const uint32_t cb = (uint32_t)(j * 16 + ((lane & 3) << 2));   // d*2 bytes
        uint32_t l0 = (uint32_t)((qrow & 127) * 128) + cb;
        uint32_t l1 = (uint32_t)(((qrow + 8) & 127) * 128) + cb;
        *(h162*)(tb + sw128(l0)) = __floats2half2_rn(oacc[j][0] * inv0, oacc[j][1] * inv0);
        *(h162*)(tb + sw128(l1)) = __floats2half2_rn(oacc[j][2] * inv1, oacc[j][3] * inv1);
    }
}

// -------------------- out-projection: bulk-copy staged, 128 thr, 4 CTAs/SM --------------------
#define OPROJ_SMEM (2 * 24576)

__global__ void __launch_bounds__(128, 4) k_oproj(
    const h16* __restrict__ wbt, const h16* __restrict__ ohq,
    const float* __restrict__ bo, const float* __restrict__ xres,
    float* __restrict__ out)
{
    extern __shared__ char smo[];
    __shared__ uint64_t mbar[2];
    const uint32_t sb = smem_u32(smo);
    const uint32_t mb0 = smem_u32(&mbar[0]);
    const uint32_t mb1 = smem_u32(&mbar[1]);

    const int b = blockIdx.z;
    const int mt = blockIdx.y, qt = blockIdx.x;
    const int m0 = mt * 64, n0 = qt * 128;
    const float* R = xres + (size_t)b * CN;
    float* Y = out + (size_t)b * CN;

    const char* Asrc = (const char*)wbt + ((size_t)3 * 8 + mt) * 8 * 8192;
    const char* Bsrc = (const char*)ohq + ((size_t)b * 8 + qt) * 8 * 16384;

    const int tid = threadIdx.x;
    const int lane = tid & 31;
    const int wn = tid >> 5;

    if (tid == 0) { MBAR_INIT(mb0, 1); MBAR_INIT(mb1, 1); }
    __syncthreads();
    if (tid == 0) {
        MBAR_EXPECT(mb0, 24576);
        CP_BULK(sb,        Asrc, 8192,  mb0);
        CP_BULK(sb + 8192, Bsrc, 16384, mb0);
    }

    const uint32_t a_off = (uint32_t)((lane & 15) * 128 + (lane >> 4) * 16);
    const int brow = ((lane >> 4) & 1) * 8 + (lane & 7);
    const uint32_t b_coff = (uint32_t)(((lane >> 3) & 1) * 16);

    float acc[4][4][4] = {};
    int ph0 = 0, ph1 = 0;

    #pragma unroll 1
    for (int s = 0; s < 8; s++) {
        if (s & 1) { MBAR_WAIT(mb1, ph1); ph1 ^= 1; }
        else       { MBAR_WAIT(mb0, ph0); ph0 ^= 1; }
        __syncthreads();
        if (s + 1 < 8 && tid == 0) {
            const uint32_t mn = ((s + 1) & 1) ? mb1 : mb0;
            const uint32_t dst = sb + ((s + 1) & 1) * 24576;
            MBAR_EXPECT(mn, 24576);
            CP_BULK(dst,        Asrc + (size_t)(s + 1) * 8192,  8192,  mn);
            CP_BULK(dst + 8192, Bsrc + (size_t)(s + 1) * 16384, 16384, mn);
        }
        const uint32_t Ab = sb + (s & 1) * 24576;
        const uint32_t Bbs = Ab + 8192;
        #pragma unroll
        for (int k16 = 0; k16 < 4; k16++) {
            uint32_t a[4][4], bb[2][4];
            #pragma unroll
            for (int mt2 = 0; mt2 < 4; mt2++)
                ldsm4(a[mt2][0], a[mt2][1], a[mt2][2], a[mt2][3],
                      Ab + sw128((uint32_t)(mt2 * 16) * 128 + a_off + k16 * 32));
            #pragma unroll
            for (int nt = 0; nt < 2; nt++)
                ldsm4(bb[nt][0], bb[nt][1], bb[nt][2], bb[nt][3],
                      Bbs + sw128((uint32_t)(wn * 32 + nt * 16 + brow) * 128 + k16 * 32 + b_coff));
            #pragma unroll
            for (int mt2 = 0; mt2 < 4; mt2++)
                #pragma unroll
                for (int ni = 0; ni < 4; ni++)
                    mma16816f(acc[mt2][ni], a[mt2], bb[ni >> 1][(ni & 1) * 2], bb[ni >> 1][(ni & 1) * 2 + 1]);
        }
    }

    #pragma unroll
    for (int mt2 = 0; mt2 < 4; mt2++) {
        const int row = m0 + mt2 * 16 + (lane >> 2);
        const float b0v = bo[row], b1v = bo[row + 8];
        #pragma unroll
        for (int ni = 0; ni < 4; ni++) {
            const int col = n0 + wn * 32 + ni * 8 + ((lane & 3) << 1);
            float2 r0 = *(const float2*)(R + (size_t)row * NN + col);
            float2 r1 = *(const float2*)(R + (size_t)(row + 8) * NN + col);
            float2 o0, o1;
            o0.x = acc[mt2][ni][0] + b0v + r0.x;
            o0.y = acc[mt2][ni][1] + b0v + r0.y;
            o1.x = acc[mt2][ni][2] + b1v + r1.x;
            o1.y = acc[mt2][ni][3] + b1v + r1.y;
            *(float2*)(Y + (size_t)row * NN + col) = o0;
            *(float2*)(Y + (size_t)(row + 8) * NN + col) = o1;
        }
    }
}

// -------------------- launch --------------------
extern "C" void kernel_launch(void* const* d_in, const int* in_sizes, int n_in,
                              void* d_out, int out_size)
{
    const float* x        = (const float*)d_in[0];
    const float* gn_scale = (const float*)d_in[1];
    const float* gn_bias  = (const float*)d_in[2];
    const float* wq = (const float*)d_in[3];
    const float* bq = (const float*)d_in[4];
    const float* wk = (const float*)d_in[5];
    const float* bk = (const float*)d_in[6];
    const float* wv = (const float*)d_in[7];
    const float* bv = (const float*)d_in[8];
    const float* wo = (const float*)d_in[9];
    const float* bo = (const float*)d_in[10];
    float* out = (float*)d_out;

    h16 *hn, *q, *k, *v, *oh, *wb;
    cudaGetSymbolAddress((void**)&hn, g_hnb);
    cudaGetSymbolAddress((void**)&q,  g_qb);
    cudaGetSymbolAddress((void**)&k,  g_kb);
    cudaGetSymbolAddress((void**)&v,  g_vb);
    cudaGetSymbolAddress((void**)&oh, g_ohb);
    cudaGetSymbolAddress((void**)&wb, g_wb);

    static int attrs_set = 0;
    if (!attrs_set) {
        cudaFuncSetAttribute(k_attn,  cudaFuncAttributeMaxDynamicSharedMemorySize, ATTN_SMEM);
        cudaFuncSetAttribute(k_qkv,   cudaFuncAttributeMaxDynamicSharedMemorySize, QKV_SMEM);
        cudaFuncSetAttribute(k_oproj, cudaFuncAttributeMaxDynamicSharedMemorySize, OPROJ_SMEM);
        attrs_set = 1;
    }

    // 1. GroupNorm -> tiled fp16 (+ weight convert -> tiled fp16)
    k_gncvt<<<Bb * GROUPS + 1024, 256>>>(x, gn_scale, gn_bias, hn, wq, wk, wv, wo, wb);

    // 2. Q/K/V projections (bulk-copy staged; Q pre-scaled by 0.125*log2 e)
    k_qkv<<<dim3(8, 8, Bb * 3), 128, QKV_SMEM>>>(wb, hn, bq, bk, bv, q, k, v);

    // 3. fused attention (outputs tiled ohq)
    k_attn<<<dim3(NN / 64, Bb * HEADS), 128, ATTN_SMEM>>>(q, k, v, oh);

    // 4. out = wo * oh + bo + x (bulk-copy staged)
    k_oproj<<<dim3(8, 8, Bb), 128, OPROJ_SMEM>>>(wb, oh, bo, x, out);
}